// round 3
// baseline (speedup 1.0000x reference)
#include <cuda_runtime.h>
#include <cuda_bf16.h>
#include <math.h>
#include <cstdint>

// Problem constants
constexpr int B_ = 2, T_ = 2048, C_ = 2048, H_ = 16, HD_ = 128;
constexpr int M_ = B_ * T_;          // 4096
constexpr int NQKV = 3 * C_;         // 6144

// Scratch (allocation-free: __device__ globals)
__device__ float g_Q[(size_t)B_ * H_ * T_ * HD_];   // [B,H,T,HD] fp32
__device__ float g_K[(size_t)B_ * H_ * T_ * HD_];
__device__ float g_V[(size_t)B_ * H_ * T_ * HD_];
__device__ float g_Y[(size_t)M_ * C_];              // attention out, tf32-rounded
__device__ float g_xA[(size_t)M_ * C_];             // x, tf32-rounded  [M,K]
__device__ float g_WqkvB[(size_t)NQKV * C_];        // Wqkv^T, tf32     [N,K]
__device__ float g_WprojB[(size_t)C_ * C_];         // Wproj^T, tf32    [N,K]

// ---------------------------------------------------------------------------
// Helpers
// ---------------------------------------------------------------------------
__device__ __forceinline__ uint32_t smem_to_u32(const void* p) {
    uint32_t a;
    asm("{ .reg .u64 t; cvta.to.shared.u64 t, %1; cvt.u32.u64 %0, t; }"
        : "=r"(a) : "l"(p));
    return a;
}
__device__ __forceinline__ void cp_async16(uint32_t smem_addr, const void* gptr) {
    asm volatile("cp.async.cg.shared.global [%0], [%1], 16;"
                 :: "r"(smem_addr), "l"(gptr) : "memory");
}
#define CP_ASYNC_COMMIT() asm volatile("cp.async.commit_group;" ::: "memory")
#define CP_ASYNC_WAIT_ALL() asm volatile("cp.async.wait_group 0;" ::: "memory")

__device__ __forceinline__ float rna_tf32(float x) {
    uint32_t u;
    asm("cvt.rna.tf32.f32 %0, %1;" : "=r"(u) : "f"(x));
    return __uint_as_float(u);
}

// m16n8k8 tf32 MMA (sm_80+ baseline PTX; lowers to tensor-pipe HMMA on sm_103)
__device__ __forceinline__ void mma_tf32(float c[4],
                                         uint32_t a0, uint32_t a1, uint32_t a2, uint32_t a3,
                                         uint32_t b0, uint32_t b1) {
    asm volatile(
        "mma.sync.aligned.m16n8k8.row.col.f32.tf32.tf32.f32 "
        "{%0,%1,%2,%3}, {%4,%5,%6,%7}, {%8,%9}, {%0,%1,%2,%3};"
        : "+f"(c[0]), "+f"(c[1]), "+f"(c[2]), "+f"(c[3])
        : "r"(a0), "r"(a1), "r"(a2), "r"(a3), "r"(b0), "r"(b1));
}

// ---------------------------------------------------------------------------
// Pre-pass 1: elementwise tf32 rounding (x -> g_xA)
// ---------------------------------------------------------------------------
__global__ void __launch_bounds__(256)
cvt_tf32(const float* __restrict__ in, float* __restrict__ out) {
    size_t i = ((size_t)blockIdx.x * 256 + threadIdx.x) * 4;
    float4 v = *(const float4*)(in + i);
    v.x = rna_tf32(v.x); v.y = rna_tf32(v.y);
    v.z = rna_tf32(v.z); v.w = rna_tf32(v.w);
    *(float4*)(out + i) = v;
}

// ---------------------------------------------------------------------------
// Pre-pass 2: transpose + tf32 round. in [R, Cc] -> out [Cc, R]
// ---------------------------------------------------------------------------
__global__ void __launch_bounds__(256)
transpose_tf32(const float* __restrict__ in, float* __restrict__ out,
               int R, int Cc) {
    __shared__ float tile[32][33];
    const int c0 = blockIdx.x * 32, r0 = blockIdx.y * 32;
    const int tx = threadIdx.x, ty = threadIdx.y;
    #pragma unroll
    for (int i = 0; i < 4; i++) {
        int r = ty + i * 8;
        tile[r][tx] = rna_tf32(in[(size_t)(r0 + r) * Cc + c0 + tx]);
    }
    __syncthreads();
    #pragma unroll
    for (int i = 0; i < 4; i++) {
        int c = ty + i * 8;
        out[(size_t)(c0 + c) * R + r0 + tx] = tile[tx][c];
    }
}

// ---------------------------------------------------------------------------
// Tensor-core tf32 GEMM: D[m][n] = sum_k A[m][k] * Bt[n][k]
// BM=BN=128, BK=32, 256 threads (8 warps, 64x32 warp tiles), cp.async
// double-buffered. A tile [m][k] stride 36, B tile [n][k] stride 36.
// mode 0: out[m][n] = D + bias[n]  (row-major, ld = ldo)
// mode 1: QKV scatter into g_Q/g_K/g_V [B,H,T,HD]
// ---------------------------------------------------------------------------
constexpr int GEMM_STAGE_FLOATS = 2 * 128 * 36;               // A+B per stage
constexpr int GEMM_SMEM_BYTES   = 2 * GEMM_STAGE_FLOATS * 4;  // 73728

__global__ void __launch_bounds__(256, 2)
gemm_tf32(const float* __restrict__ A, const float* __restrict__ Bt,
          const float* __restrict__ bias, float* __restrict__ out,
          int K, int mode, int ldo) {
    extern __shared__ float sm[];
    const uint32_t sb = smem_to_u32(sm);
    const int tid = threadIdx.x;
    const int wid = tid >> 5, lane = tid & 31;
    const int bm = blockIdx.y, bn = blockIdx.x;
    const int wm = (wid >> 2) * 64;      // warp m offset (0 / 64)
    const int wn = (wid & 3) * 32;       // warp n offset (0/32/64/96)

    float acc[4][4][4];
    #pragma unroll
    for (int mi = 0; mi < 4; mi++)
        #pragma unroll
        for (int ni = 0; ni < 4; ni++)
            #pragma unroll
            for (int q = 0; q < 4; q++) acc[mi][ni][q] = 0.f;

    const float* gA = A  + (size_t)bm * 128 * K;
    const float* gB = Bt + (size_t)bn * 128 * K;

    // stage s: A at byte offset s*36864, B at +18432 within the stage
    auto load_stage = [&](int s, int k0) {
        const uint32_t base = sb + (uint32_t)s * (GEMM_STAGE_FLOATS * 4);
        #pragma unroll
        for (int i = 0; i < 4; i++) {
            int u = i * 256 + tid;
            int r = u >> 3, c = u & 7;
            cp_async16(base + r * 144 + c * 16, gA + (size_t)r * K + k0 + c * 4);
        }
        #pragma unroll
        for (int i = 0; i < 4; i++) {
            int u = i * 256 + tid;
            int r = u >> 3, c = u & 7;
            cp_async16(base + 18432 + r * 144 + c * 16,
                       gB + (size_t)r * K + k0 + c * 4);
        }
    };

    load_stage(0, 0);
    CP_ASYNC_COMMIT();

    const int NT = K / 32;
    for (int j = 0; j < NT; j++) {
        CP_ASYNC_WAIT_ALL();
        __syncthreads();    // stage j visible; prior compute done before overwrite

        if (j + 1 < NT) {
            load_stage((j + 1) & 1, (j + 1) * 32);
            CP_ASYNC_COMMIT();
        }

        const float* As = sm + (j & 1) * GEMM_STAGE_FLOATS;
        const float* Bs = As + 128 * 36;

        #pragma unroll
        for (int ks = 0; ks < 4; ks++) {
            const int kb = ks * 8 + (lane & 3);
            uint32_t a[4][4], b[4][2];
            #pragma unroll
            for (int mi = 0; mi < 4; mi++) {
                int r = wm + mi * 16 + (lane >> 2);
                a[mi][0] = __float_as_uint(As[r * 36 + kb]);
                a[mi][1] = __float_as_uint(As[(r + 8) * 36 + kb]);
                a[mi][2] = __float_as_uint(As[r * 36 + kb + 4]);
                a[mi][3] = __float_as_uint(As[(r + 8) * 36 + kb + 4]);
            }
            #pragma unroll
            for (int ni = 0; ni < 4; ni++) {
                int r = wn + ni * 8 + (lane >> 2);
                b[ni][0] = __float_as_uint(Bs[r * 36 + kb]);
                b[ni][1] = __float_as_uint(Bs[r * 36 + kb + 4]);
            }
            #pragma unroll
            for (int mi = 0; mi < 4; mi++)
                #pragma unroll
                for (int ni = 0; ni < 4; ni++)
                    mma_tf32(acc[mi][ni], a[mi][0], a[mi][1], a[mi][2], a[mi][3],
                             b[ni][0], b[ni][1]);
        }
        __syncthreads();
    }

    // Epilogue. Fragment: c0,c1 at (row, col), (row, col+1); c2,c3 at row+8.
    const int fr = lane >> 2;
    const int fc = (lane & 3) * 2;

    if (mode == 1) {
        const int b  = bm >> 4;
        const int t0 = (bm & 15) * 128;
        const int n0g = bn * 128;
        const int s  = n0g >> 11;
        const int h  = (n0g & 2047) >> 7;
        float* base = ((s == 0) ? g_Q : (s == 1) ? g_K : g_V)
                      + (size_t)(b * H_ + h) * T_ * HD_;
        #pragma unroll
        for (int mi = 0; mi < 4; mi++) {
            #pragma unroll
            for (int ni = 0; ni < 4; ni++) {
                int m = wm + mi * 16 + fr;
                int n = wn + ni * 8 + fc;
                float* p0 = base + (size_t)(t0 + m) * HD_ + n;
                float* p1 = base + (size_t)(t0 + m + 8) * HD_ + n;
                *(float2*)p0 = make_float2(acc[mi][ni][0], acc[mi][ni][1]);
                *(float2*)p1 = make_float2(acc[mi][ni][2], acc[mi][ni][3]);
            }
        }
    } else {
        #pragma unroll
        for (int mi = 0; mi < 4; mi++) {
            #pragma unroll
            for (int ni = 0; ni < 4; ni++) {
                int m = bm * 128 + wm + mi * 16 + fr;
                int n = bn * 128 + wn + ni * 8 + fc;
                float b0 = bias[n], b1 = bias[n + 1];
                float* p0 = out + (size_t)m * ldo + n;
                float* p1 = out + (size_t)(m + 8) * ldo + n;
                *(float2*)p0 = make_float2(acc[mi][ni][0] + b0, acc[mi][ni][1] + b1);
                *(float2*)p1 = make_float2(acc[mi][ni][2] + b0, acc[mi][ni][3] + b1);
            }
        }
    }
}

// ---------------------------------------------------------------------------
// Flash-attention, fp32, causal. Br=Bc=64, HD=128, 256 threads.
// ---------------------------------------------------------------------------
constexpr int QS_STRIDE = 129;
constexpr int SS_STRIDE = 65;
constexpr int ATTN_SMEM_FLOATS = 64 * QS_STRIDE * 2 + 64 * HD_ + 64 * SS_STRIDE;
constexpr int ATTN_SMEM_BYTES  = ATTN_SMEM_FLOATS * 4;   // 115,456 B

__global__ void __launch_bounds__(256)
attn_kernel() {
    extern __shared__ float sm[];
    float* Qs = sm;
    float* Ks = Qs + 64 * QS_STRIDE;
    float* Vs = Ks + 64 * QS_STRIDE;
    float* Ss = Vs + 64 * HD_;

    const int tid = threadIdx.x;
    const int qi = blockIdx.x, h = blockIdx.y, b = blockIdx.z;
    const int q0 = qi * 64;

    const size_t bh = (size_t)(b * H_ + h) * T_ * HD_;
    const float* Qg = g_Q + bh;
    const float* Kg = g_K + bh;
    const float* Vg = g_V + bh;

    constexpr float SCALE = 0.08838834764831845f;
    for (int e = tid; e < 64 * HD_; e += 256) {
        int r = e >> 7, c = e & 127;
        Qs[r * QS_STRIDE + c] = Qg[(size_t)(q0 + r) * HD_ + c] * SCALE;
    }

    const int qr = tid >> 2;
    const int kb = (tid & 3) * 16;
    const int c0 = (tid & 3) * 32;

    float m = -1e30f, l = 0.f;
    float acc[32];
    #pragma unroll
    for (int j = 0; j < 32; j++) acc[j] = 0.f;

    __syncthreads();

    for (int kt = 0; kt <= qi; kt++) {
        const int k0 = kt * 64;
        for (int e = tid; e < 64 * HD_; e += 256) {
            int r = e >> 7, c = e & 127;
            Ks[r * QS_STRIDE + c] = Kg[(size_t)(k0 + r) * HD_ + c];
            Vs[r * HD_ + c]       = Vg[(size_t)(k0 + r) * HD_ + c];
        }
        __syncthreads();

        float s[16];
        #pragma unroll
        for (int j = 0; j < 16; j++) s[j] = 0.f;
        for (int d = 0; d < HD_; d++) {
            float qv = Qs[qr * QS_STRIDE + d];
            #pragma unroll
            for (int j = 0; j < 16; j++)
                s[j] = fmaf(qv, Ks[(kb + j) * QS_STRIDE + d], s[j]);
        }

        if (kt == qi) {
            #pragma unroll
            for (int j = 0; j < 16; j++)
                if (k0 + kb + j > q0 + qr) s[j] = -1e30f;
        }

        float tmax = s[0];
        #pragma unroll
        for (int j = 1; j < 16; j++) tmax = fmaxf(tmax, s[j]);
        tmax = fmaxf(tmax, __shfl_xor_sync(0xffffffffu, tmax, 1));
        tmax = fmaxf(tmax, __shfl_xor_sync(0xffffffffu, tmax, 2));

        float mnew  = fmaxf(m, tmax);
        float alpha = __expf(m - mnew);

        float psum = 0.f;
        #pragma unroll
        for (int j = 0; j < 16; j++) {
            float p = __expf(s[j] - mnew);
            Ss[qr * SS_STRIDE + kb + j] = p;
            psum += p;
        }
        psum += __shfl_xor_sync(0xffffffffu, psum, 1);
        psum += __shfl_xor_sync(0xffffffffu, psum, 2);
        l = l * alpha + psum;
        m = mnew;

        __syncthreads();

        #pragma unroll
        for (int j = 0; j < 32; j++) acc[j] *= alpha;

        for (int k = 0; k < 64; k++) {
            float p = Ss[qr * SS_STRIDE + k];
            const float4* vrow = (const float4*)(Vs + k * HD_ + c0);
            #pragma unroll
            for (int j4 = 0; j4 < 8; j4++) {
                float4 v = vrow[j4];
                acc[j4 * 4 + 0] = fmaf(p, v.x, acc[j4 * 4 + 0]);
                acc[j4 * 4 + 1] = fmaf(p, v.y, acc[j4 * 4 + 1]);
                acc[j4 * 4 + 2] = fmaf(p, v.z, acc[j4 * 4 + 2]);
                acc[j4 * 4 + 3] = fmaf(p, v.w, acc[j4 * 4 + 3]);
            }
        }
        __syncthreads();
    }

    // Normalize, round to tf32 (proj GEMM input), write
    float inv = 1.f / l;
    float* yrow = g_Y + ((size_t)(b * T_ + q0 + qr)) * C_ + h * HD_ + c0;
    #pragma unroll
    for (int j4 = 0; j4 < 8; j4++) {
        *(float4*)(yrow + j4 * 4) = make_float4(
            rna_tf32(acc[j4 * 4 + 0] * inv), rna_tf32(acc[j4 * 4 + 1] * inv),
            rna_tf32(acc[j4 * 4 + 2] * inv), rna_tf32(acc[j4 * 4 + 3] * inv));
    }
}

// ---------------------------------------------------------------------------
// Launch. Inputs (metadata order): x, mask, W_qkv, W_proj, b_proj
// ---------------------------------------------------------------------------
extern "C" void kernel_launch(void* const* d_in, const int* in_sizes, int n_in,
                              void* d_out, int out_size) {
    const float* x     = (const float*)d_in[0];
    const float* Wqkv  = (const float*)d_in[2];
    const float* Wproj = (const float*)d_in[3];
    const float* bproj = (const float*)d_in[4];
    float* out = (float*)d_out;

    static bool attr_set = false;
    if (!attr_set) {
        cudaFuncSetAttribute(attn_kernel,
                             cudaFuncAttributeMaxDynamicSharedMemorySize,
                             ATTN_SMEM_BYTES);
        cudaFuncSetAttribute(gemm_tf32,
                             cudaFuncAttributeMaxDynamicSharedMemorySize,
                             GEMM_SMEM_BYTES);
        attr_set = true;
    }

    float* g_xA_p;     cudaGetSymbolAddress((void**)&g_xA_p, g_xA);
    float* g_WqkvB_p;  cudaGetSymbolAddress((void**)&g_WqkvB_p, g_WqkvB);
    float* g_WprojB_p; cudaGetSymbolAddress((void**)&g_WprojB_p, g_WprojB);
    float* g_Y_p;      cudaGetSymbolAddress((void**)&g_Y_p, g_Y);

    // Pre-pass: tf32 rounding + weight transposes
    cvt_tf32<<<(M_ * C_) / 1024, 256>>>(x, g_xA_p);
    transpose_tf32<<<dim3(NQKV / 32, C_ / 32), dim3(32, 8)>>>(Wqkv, g_WqkvB_p, C_, NQKV);
    transpose_tf32<<<dim3(C_ / 32, C_ / 32), dim3(32, 8)>>>(Wproj, g_WprojB_p, C_, C_);

    // QKV projection (tensor cores), scatter to [B,H,T,HD]
    gemm_tf32<<<dim3(NQKV / 128, M_ / 128), 256, GEMM_SMEM_BYTES>>>(
        g_xA_p, g_WqkvB_p, nullptr, nullptr, C_, 1, 0);

    // Attention (fp32 flash, causal)
    attn_kernel<<<dim3(T_ / 64, H_, B_), 256, ATTN_SMEM_BYTES>>>();

    // Output projection (tensor cores) + bias
    gemm_tf32<<<dim3(C_ / 128, M_ / 128), 256, GEMM_SMEM_BYTES>>>(
        g_Y_p, g_WprojB_p, bproj, out, C_, 0, C_);
}

// round 4
// speedup vs baseline: 8.7840x; 8.7840x over previous
#include <cuda_runtime.h>
#include <cuda_bf16.h>
#include <math.h>
#include <cstdint>

// Problem constants
constexpr int B_ = 2, T_ = 2048, C_ = 2048, H_ = 16, HD_ = 128;
constexpr int M_ = B_ * T_;          // 4096
constexpr int NQKV = 3 * C_;         // 6144

// Scratch (allocation-free: __device__ globals)
__device__ float g_Q[(size_t)B_ * H_ * T_ * HD_];   // [B,H,T,HD] fp32
__device__ float g_K[(size_t)B_ * H_ * T_ * HD_];
__device__ float g_V[(size_t)B_ * H_ * T_ * HD_];
__device__ float g_Y[(size_t)M_ * C_];              // attention out, tf32-rounded
__device__ float g_xA[(size_t)M_ * C_];             // x, tf32-rounded  [M,K]
__device__ float g_WqkvB[(size_t)NQKV * C_];        // Wqkv^T, tf32     [N,K]
__device__ float g_WprojB[(size_t)C_ * C_];         // Wproj^T, tf32    [N,K]

// ---------------------------------------------------------------------------
// Helpers
// ---------------------------------------------------------------------------
__device__ __forceinline__ uint32_t smem_to_u32(const void* p) {
    uint32_t a;
    asm("{ .reg .u64 t; cvta.to.shared.u64 t, %1; cvt.u32.u64 %0, t; }"
        : "=r"(a) : "l"(p));
    return a;
}
__device__ __forceinline__ void cp_async16(uint32_t smem_addr, const void* gptr) {
    asm volatile("cp.async.cg.shared.global [%0], [%1], 16;"
                 :: "r"(smem_addr), "l"(gptr) : "memory");
}
#define CP_ASYNC_COMMIT() asm volatile("cp.async.commit_group;" ::: "memory")
#define CP_ASYNC_WAIT_ALL() asm volatile("cp.async.wait_group 0;" ::: "memory")

__device__ __forceinline__ float rna_tf32(float x) {
    uint32_t u;
    asm("cvt.rna.tf32.f32 %0, %1;" : "=r"(u) : "f"(x));
    return __uint_as_float(u);
}

// m16n8k8 tf32 MMA (sm_80+ baseline PTX; lowers to tensor-pipe HMMA on sm_103)
__device__ __forceinline__ void mma_tf32(float c[4],
                                         uint32_t a0, uint32_t a1, uint32_t a2, uint32_t a3,
                                         uint32_t b0, uint32_t b1) {
    asm volatile(
        "mma.sync.aligned.m16n8k8.row.col.f32.tf32.tf32.f32 "
        "{%0,%1,%2,%3}, {%4,%5,%6,%7}, {%8,%9}, {%0,%1,%2,%3};"
        : "+f"(c[0]), "+f"(c[1]), "+f"(c[2]), "+f"(c[3])
        : "r"(a0), "r"(a1), "r"(a2), "r"(a3), "r"(b0), "r"(b1));
}

// ---------------------------------------------------------------------------
// Pre-pass 1: elementwise tf32 rounding (x -> g_xA)
// ---------------------------------------------------------------------------
__global__ void __launch_bounds__(256)
cvt_tf32(const float* __restrict__ in, float* __restrict__ out) {
    size_t i = ((size_t)blockIdx.x * 256 + threadIdx.x) * 4;
    float4 v = *(const float4*)(in + i);
    v.x = rna_tf32(v.x); v.y = rna_tf32(v.y);
    v.z = rna_tf32(v.z); v.w = rna_tf32(v.w);
    *(float4*)(out + i) = v;
}

// ---------------------------------------------------------------------------
// Pre-pass 2: transpose + tf32 round. in [R, Cc] -> out [Cc, R]
// ---------------------------------------------------------------------------
__global__ void __launch_bounds__(256)
transpose_tf32(const float* __restrict__ in, float* __restrict__ out,
               int R, int Cc) {
    __shared__ float tile[32][33];
    const int c0 = blockIdx.x * 32, r0 = blockIdx.y * 32;
    const int tx = threadIdx.x, ty = threadIdx.y;
    #pragma unroll
    for (int i = 0; i < 4; i++) {
        int r = ty + i * 8;
        tile[r][tx] = rna_tf32(in[(size_t)(r0 + r) * Cc + c0 + tx]);
    }
    __syncthreads();
    #pragma unroll
    for (int i = 0; i < 4; i++) {
        int c = ty + i * 8;
        out[(size_t)(c0 + c) * R + r0 + tx] = tile[tx][c];
    }
}

// ---------------------------------------------------------------------------
// Tensor-core tf32 GEMM (unchanged from R3): D[m][n] = sum_k A[m][k]*Bt[n][k]
// ---------------------------------------------------------------------------
constexpr int GEMM_STAGE_FLOATS = 2 * 128 * 36;
constexpr int GEMM_SMEM_BYTES   = 2 * GEMM_STAGE_FLOATS * 4;  // 73728

__global__ void __launch_bounds__(256, 2)
gemm_tf32(const float* __restrict__ A, const float* __restrict__ Bt,
          const float* __restrict__ bias, float* __restrict__ out,
          int K, int mode, int ldo) {
    extern __shared__ float sm[];
    const uint32_t sb = smem_to_u32(sm);
    const int tid = threadIdx.x;
    const int wid = tid >> 5, lane = tid & 31;
    const int bm = blockIdx.y, bn = blockIdx.x;
    const int wm = (wid >> 2) * 64;
    const int wn = (wid & 3) * 32;

    float acc[4][4][4];
    #pragma unroll
    for (int mi = 0; mi < 4; mi++)
        #pragma unroll
        for (int ni = 0; ni < 4; ni++)
            #pragma unroll
            for (int q = 0; q < 4; q++) acc[mi][ni][q] = 0.f;

    const float* gA = A  + (size_t)bm * 128 * K;
    const float* gB = Bt + (size_t)bn * 128 * K;

    auto load_stage = [&](int s, int k0) {
        const uint32_t base = sb + (uint32_t)s * (GEMM_STAGE_FLOATS * 4);
        #pragma unroll
        for (int i = 0; i < 4; i++) {
            int u = i * 256 + tid;
            int r = u >> 3, c = u & 7;
            cp_async16(base + r * 144 + c * 16, gA + (size_t)r * K + k0 + c * 4);
        }
        #pragma unroll
        for (int i = 0; i < 4; i++) {
            int u = i * 256 + tid;
            int r = u >> 3, c = u & 7;
            cp_async16(base + 18432 + r * 144 + c * 16,
                       gB + (size_t)r * K + k0 + c * 4);
        }
    };

    load_stage(0, 0);
    CP_ASYNC_COMMIT();

    const int NT = K / 32;
    for (int j = 0; j < NT; j++) {
        CP_ASYNC_WAIT_ALL();
        __syncthreads();

        if (j + 1 < NT) {
            load_stage((j + 1) & 1, (j + 1) * 32);
            CP_ASYNC_COMMIT();
        }

        const float* As = sm + (j & 1) * GEMM_STAGE_FLOATS;
        const float* Bs = As + 128 * 36;

        #pragma unroll
        for (int ks = 0; ks < 4; ks++) {
            const int kb = ks * 8 + (lane & 3);
            uint32_t a[4][4], b[4][2];
            #pragma unroll
            for (int mi = 0; mi < 4; mi++) {
                int r = wm + mi * 16 + (lane >> 2);
                a[mi][0] = __float_as_uint(As[r * 36 + kb]);
                a[mi][1] = __float_as_uint(As[(r + 8) * 36 + kb]);
                a[mi][2] = __float_as_uint(As[r * 36 + kb + 4]);
                a[mi][3] = __float_as_uint(As[(r + 8) * 36 + kb + 4]);
            }
            #pragma unroll
            for (int ni = 0; ni < 4; ni++) {
                int r = wn + ni * 8 + (lane >> 2);
                b[ni][0] = __float_as_uint(Bs[r * 36 + kb]);
                b[ni][1] = __float_as_uint(Bs[r * 36 + kb + 4]);
            }
            #pragma unroll
            for (int mi = 0; mi < 4; mi++)
                #pragma unroll
                for (int ni = 0; ni < 4; ni++)
                    mma_tf32(acc[mi][ni], a[mi][0], a[mi][1], a[mi][2], a[mi][3],
                             b[ni][0], b[ni][1]);
        }
        __syncthreads();
    }

    const int fr = lane >> 2;
    const int fc = (lane & 3) * 2;

    if (mode == 1) {
        const int b  = bm >> 4;
        const int t0 = (bm & 15) * 128;
        const int n0g = bn * 128;
        const int s  = n0g >> 11;
        const int h  = (n0g & 2047) >> 7;
        float* base = ((s == 0) ? g_Q : (s == 1) ? g_K : g_V)
                      + (size_t)(b * H_ + h) * T_ * HD_;
        #pragma unroll
        for (int mi = 0; mi < 4; mi++) {
            #pragma unroll
            for (int ni = 0; ni < 4; ni++) {
                int m = wm + mi * 16 + fr;
                int n = wn + ni * 8 + fc;
                float* p0 = base + (size_t)(t0 + m) * HD_ + n;
                float* p1 = base + (size_t)(t0 + m + 8) * HD_ + n;
                *(float2*)p0 = make_float2(acc[mi][ni][0], acc[mi][ni][1]);
                *(float2*)p1 = make_float2(acc[mi][ni][2], acc[mi][ni][3]);
            }
        }
    } else {
        #pragma unroll
        for (int mi = 0; mi < 4; mi++) {
            #pragma unroll
            for (int ni = 0; ni < 4; ni++) {
                int m = bm * 128 + wm + mi * 16 + fr;
                int n = bn * 128 + wn + ni * 8 + fc;
                float b0 = bias[n], b1 = bias[n + 1];
                float* p0 = out + (size_t)m * ldo + n;
                float* p1 = out + (size_t)(m + 8) * ldo + n;
                *(float2*)p0 = make_float2(acc[mi][ni][0] + b0, acc[mi][ni][1] + b1);
                *(float2*)p1 = make_float2(acc[mi][ni][2] + b0, acc[mi][ni][3] + b1);
            }
        }
    }
}

// ---------------------------------------------------------------------------
// Tensor-core flash attention (tf32 m16n8k8), causal.
// Br=128, Bc=64, HD=128, 8 warps; warp w owns q-rows [w*16, w*16+16).
// Smem strides chosen so all MMA-fragment LDS are conflict-free:
//   bank(row*stride + tq) = 4*(lane>>2) + (lane&3)  (perfect permutation)
// ---------------------------------------------------------------------------
constexpr int AQ_ST = 132;   // Qs/Ks row stride (floats)
constexpr int AV_ST = 68;    // Vt/Ps row stride (floats)
constexpr int ATTN_SMEM_FLOATS =
    128 * AQ_ST +            // Qs [128][132]
    64 * AQ_ST +             // Ks [64][132]
    128 * AV_ST +            // Vt [128][68]  (V transposed: Vt[d][k])
    128 * AV_ST;             // Ps [128][68]
constexpr int ATTN_SMEM_BYTES = ATTN_SMEM_FLOATS * 4;   // 171,008 B

__global__ void __launch_bounds__(256)
attn_mma() {
    extern __shared__ float sm[];
    float* Qs = sm;
    float* Ks = Qs + 128 * AQ_ST;
    float* Vt = Ks + 64 * AQ_ST;
    float* Ps = Vt + 128 * AV_ST;
    const uint32_t ks_base = smem_to_u32(Ks);

    const int tid = threadIdx.x;
    const int w = tid >> 5, lane = tid & 31;
    const int qi = blockIdx.x, h = blockIdx.y, b = blockIdx.z;
    const int q0 = qi * 128;

    const size_t bh = (size_t)(b * H_ + h) * T_ * HD_;
    const float* Qg = g_Q + bh;
    const float* Kg = g_K + bh;
    const float* Vg = g_V + bh;

    // Load Q tile [128][128], pre-scaled + tf32-rounded
    constexpr float SCALE = 0.08838834764831845f;   // 128^-0.5
    #pragma unroll
    for (int i = 0; i < 16; i++) {
        int u = i * 256 + tid;
        int r = u >> 5, c4 = u & 31;
        float4 v = *(const float4*)(Qg + (size_t)(q0 + r) * HD_ + c4 * 4);
        v.x = rna_tf32(v.x * SCALE); v.y = rna_tf32(v.y * SCALE);
        v.z = rna_tf32(v.z * SCALE); v.w = rna_tf32(v.w * SCALE);
        *(float4*)(Qs + r * AQ_ST + c4 * 4) = v;
    }

    const int fr = lane >> 2;          // fragment row (0..7)
    const int tq = lane & 3;           // fragment k/col lane
    const int qrow0 = q0 + w * 16 + fr;
    const int qrow1 = qrow0 + 8;

    float m0 = -1e30f, m1 = -1e30f, l0 = 0.f, l1 = 0.f;
    float o[16][4];
    #pragma unroll
    for (int nf = 0; nf < 16; nf++)
        #pragma unroll
        for (int q = 0; q < 4; q++) o[nf][q] = 0.f;

    __syncthreads();

    const int nkt = 2 * qi + 2;
    for (int kt = 0; kt < nkt; kt++) {
        const int k0 = kt * 64;

        // K tile [64][128] via cp.async
        #pragma unroll
        for (int i = 0; i < 8; i++) {
            int u = i * 256 + tid;
            int r = u >> 5, c4 = u & 31;
            cp_async16(ks_base + (uint32_t)(r * AQ_ST + c4 * 4) * 4,
                       Kg + (size_t)(k0 + r) * HD_ + c4 * 4);
        }
        CP_ASYNC_COMMIT();

        // V tile transposed into Vt[d][k], tf32-rounded
        #pragma unroll
        for (int i = 0; i < 8; i++) {
            int u = i * 256 + tid;
            int r = u >> 5, c4 = u & 31;
            float4 v = *(const float4*)(Vg + (size_t)(k0 + r) * HD_ + c4 * 4);
            Vt[(c4 * 4 + 0) * AV_ST + r] = rna_tf32(v.x);
            Vt[(c4 * 4 + 1) * AV_ST + r] = rna_tf32(v.y);
            Vt[(c4 * 4 + 2) * AV_ST + r] = rna_tf32(v.z);
            Vt[(c4 * 4 + 3) * AV_ST + r] = rna_tf32(v.w);
        }
        CP_ASYNC_WAIT_ALL();
        // round the K elements this thread loaded (in place)
        #pragma unroll
        for (int i = 0; i < 8; i++) {
            int u = i * 256 + tid;
            int r = u >> 5, c4 = u & 31;
            float4 v = *(float4*)(Ks + r * AQ_ST + c4 * 4);
            v.x = rna_tf32(v.x); v.y = rna_tf32(v.y);
            v.z = rna_tf32(v.z); v.w = rna_tf32(v.w);
            *(float4*)(Ks + r * AQ_ST + c4 * 4) = v;
        }
        __syncthreads();

        // ---- S = Q K^T (warp rows [w*16, +16) x 64 cols) ----
        float s[8][4];
        #pragma unroll
        for (int nf = 0; nf < 8; nf++)
            #pragma unroll
            for (int q = 0; q < 4; q++) s[nf][q] = 0.f;

        #pragma unroll
        for (int ks = 0; ks < 16; ks++) {
            const int kb = ks * 8 + tq;
            const int ra = w * 16 + fr;
            uint32_t a0 = __float_as_uint(Qs[ra * AQ_ST + kb]);
            uint32_t a1 = __float_as_uint(Qs[(ra + 8) * AQ_ST + kb]);
            uint32_t a2 = __float_as_uint(Qs[ra * AQ_ST + kb + 4]);
            uint32_t a3 = __float_as_uint(Qs[(ra + 8) * AQ_ST + kb + 4]);
            #pragma unroll
            for (int nf = 0; nf < 8; nf++) {
                const int rb = nf * 8 + fr;
                uint32_t b0 = __float_as_uint(Ks[rb * AQ_ST + kb]);
                uint32_t b1 = __float_as_uint(Ks[rb * AQ_ST + kb + 4]);
                mma_tf32(s[nf], a0, a1, a2, a3, b0, b1);
            }
        }

        // ---- causal mask (only needed on the last two k-tiles) ----
        if (kt >= 2 * qi) {
            #pragma unroll
            for (int nf = 0; nf < 8; nf++) {
                int col = k0 + nf * 8 + 2 * tq;
                if (col     > qrow0) s[nf][0] = -1e30f;
                if (col + 1 > qrow0) s[nf][1] = -1e30f;
                if (col     > qrow1) s[nf][2] = -1e30f;
                if (col + 1 > qrow1) s[nf][3] = -1e30f;
            }
        }

        // ---- online softmax (rows fr / fr+8; 4 lanes share a row) ----
        float mx0 = -1e30f, mx1 = -1e30f;
        #pragma unroll
        for (int nf = 0; nf < 8; nf++) {
            mx0 = fmaxf(mx0, fmaxf(s[nf][0], s[nf][1]));
            mx1 = fmaxf(mx1, fmaxf(s[nf][2], s[nf][3]));
        }
        mx0 = fmaxf(mx0, __shfl_xor_sync(0xffffffffu, mx0, 1));
        mx0 = fmaxf(mx0, __shfl_xor_sync(0xffffffffu, mx0, 2));
        mx1 = fmaxf(mx1, __shfl_xor_sync(0xffffffffu, mx1, 1));
        mx1 = fmaxf(mx1, __shfl_xor_sync(0xffffffffu, mx1, 2));

        float mn0 = fmaxf(m0, mx0), mn1 = fmaxf(m1, mx1);
        float al0 = __expf(m0 - mn0), al1 = __expf(m1 - mn1);

        float ps0 = 0.f, ps1 = 0.f;
        const int pr0 = (w * 16 + fr) * AV_ST;
        const int pr1 = pr0 + 8 * AV_ST;
        #pragma unroll
        for (int nf = 0; nf < 8; nf++) {
            float p0 = __expf(s[nf][0] - mn0);
            float p1 = __expf(s[nf][1] - mn0);
            float p2 = __expf(s[nf][2] - mn1);
            float p3 = __expf(s[nf][3] - mn1);
            ps0 += p0 + p1; ps1 += p2 + p3;
            int c = nf * 8 + 2 * tq;
            *(float2*)(Ps + pr0 + c) = make_float2(rna_tf32(p0), rna_tf32(p1));
            *(float2*)(Ps + pr1 + c) = make_float2(rna_tf32(p2), rna_tf32(p3));
        }
        ps0 += __shfl_xor_sync(0xffffffffu, ps0, 1);
        ps0 += __shfl_xor_sync(0xffffffffu, ps0, 2);
        ps1 += __shfl_xor_sync(0xffffffffu, ps1, 1);
        ps1 += __shfl_xor_sync(0xffffffffu, ps1, 2);
        l0 = l0 * al0 + ps0; m0 = mn0;
        l1 = l1 * al1 + ps1; m1 = mn1;

        // rescale output accumulators
        #pragma unroll
        for (int nf = 0; nf < 16; nf++) {
            o[nf][0] *= al0; o[nf][1] *= al0;
            o[nf][2] *= al1; o[nf][3] *= al1;
        }

        __syncwarp();   // Ps rows are warp-private; order STS -> LDS in-warp

        // ---- O += P V  (P: [16 x 64] A-frags, V^T: [128 n][64 k] B-frags) ----
        #pragma unroll
        for (int ks2 = 0; ks2 < 8; ks2++) {
            const int kb = ks2 * 8 + tq;
            uint32_t a0 = __float_as_uint(Ps[pr0 + kb]);
            uint32_t a1 = __float_as_uint(Ps[pr1 + kb]);
            uint32_t a2 = __float_as_uint(Ps[pr0 + kb + 4]);
            uint32_t a3 = __float_as_uint(Ps[pr1 + kb + 4]);
            #pragma unroll
            for (int nf = 0; nf < 16; nf++) {
                const int rb = nf * 8 + fr;
                uint32_t b0 = __float_as_uint(Vt[rb * AV_ST + kb]);
                uint32_t b1 = __float_as_uint(Vt[rb * AV_ST + kb + 4]);
                mma_tf32(o[nf], a0, a1, a2, a3, b0, b1);
            }
        }
        __syncthreads();   // before next tile overwrites Ks/Vt
    }

    // ---- epilogue: normalize, tf32-round (proj GEMM input), write ----
    const float inv0 = 1.f / l0, inv1 = 1.f / l1;
    float* y0 = g_Y + (size_t)(b * T_ + qrow0) * C_ + h * HD_;
    float* y1 = g_Y + (size_t)(b * T_ + qrow1) * C_ + h * HD_;
    #pragma unroll
    for (int nf = 0; nf < 16; nf++) {
        int c = nf * 8 + 2 * tq;
        *(float2*)(y0 + c) = make_float2(rna_tf32(o[nf][0] * inv0),
                                         rna_tf32(o[nf][1] * inv0));
        *(float2*)(y1 + c) = make_float2(rna_tf32(o[nf][2] * inv1),
                                         rna_tf32(o[nf][3] * inv1));
    }
}

// ---------------------------------------------------------------------------
// Launch. Inputs (metadata order): x, mask, W_qkv, W_proj, b_proj
// ---------------------------------------------------------------------------
extern "C" void kernel_launch(void* const* d_in, const int* in_sizes, int n_in,
                              void* d_out, int out_size) {
    const float* x     = (const float*)d_in[0];
    const float* Wqkv  = (const float*)d_in[2];
    const float* Wproj = (const float*)d_in[3];
    const float* bproj = (const float*)d_in[4];
    float* out = (float*)d_out;

    static bool attr_set = false;
    if (!attr_set) {
        cudaFuncSetAttribute(attn_mma,
                             cudaFuncAttributeMaxDynamicSharedMemorySize,
                             ATTN_SMEM_BYTES);
        cudaFuncSetAttribute(gemm_tf32,
                             cudaFuncAttributeMaxDynamicSharedMemorySize,
                             GEMM_SMEM_BYTES);
        attr_set = true;
    }

    float* g_xA_p;     cudaGetSymbolAddress((void**)&g_xA_p, g_xA);
    float* g_WqkvB_p;  cudaGetSymbolAddress((void**)&g_WqkvB_p, g_WqkvB);
    float* g_WprojB_p; cudaGetSymbolAddress((void**)&g_WprojB_p, g_WprojB);
    float* g_Y_p;      cudaGetSymbolAddress((void**)&g_Y_p, g_Y);

    // Pre-pass: tf32 rounding + weight transposes
    cvt_tf32<<<(M_ * C_) / 1024, 256>>>(x, g_xA_p);
    transpose_tf32<<<dim3(NQKV / 32, C_ / 32), dim3(32, 8)>>>(Wqkv, g_WqkvB_p, C_, NQKV);
    transpose_tf32<<<dim3(C_ / 32, C_ / 32), dim3(32, 8)>>>(Wproj, g_WprojB_p, C_, C_);

    // QKV projection (tensor cores), scatter to [B,H,T,HD]
    gemm_tf32<<<dim3(NQKV / 128, M_ / 128), 256, GEMM_SMEM_BYTES>>>(
        g_xA_p, g_WqkvB_p, nullptr, nullptr, C_, 1, 0);

    // Attention (tf32 tensor-core flash, causal)
    attn_mma<<<dim3(T_ / 128, H_, B_), 256, ATTN_SMEM_BYTES>>>();

    // Output projection (tensor cores) + bias
    gemm_tf32<<<dim3(C_ / 128, M_ / 128), 256, GEMM_SMEM_BYTES>>>(
        g_Y_p, g_WprojB_p, bproj, out, C_, 0, C_);
}

// round 5
// speedup vs baseline: 18.4788x; 2.1037x over previous
#include <cuda_runtime.h>
#include <cuda_fp16.h>
#include <math.h>
#include <cstdint>

// Problem constants
constexpr int B_ = 2, T_ = 2048, C_ = 2048, H_ = 16, HD_ = 128;
constexpr int M_ = B_ * T_;          // 4096
constexpr int NQKV = 3 * C_;         // 6144

// Scratch (allocation-free: __device__ globals), fp16 operands everywhere
__device__ __half g_Qh[(size_t)B_ * H_ * T_ * HD_];   // [B,H,T,HD], pre-scaled
__device__ __half g_Kh[(size_t)B_ * H_ * T_ * HD_];   // [B,H,T,HD]
__device__ __half g_Vt[(size_t)B_ * H_ * HD_ * T_];   // [B,H,D,T]  (d-major!)
__device__ __half g_Yh[(size_t)M_ * C_];              // attention out [M,C]
__device__ __half g_xh[(size_t)M_ * C_];              // x, fp16       [M,K]
__device__ __half g_Wqkvh[(size_t)NQKV * C_];         // Wqkv^T, fp16  [N,K]
__device__ __half g_Wprojh[(size_t)C_ * C_];          // Wproj^T, fp16 [N,K]

// ---------------------------------------------------------------------------
// Helpers
// ---------------------------------------------------------------------------
__device__ __forceinline__ uint32_t smem_to_u32(const void* p) {
    uint32_t a;
    asm("{ .reg .u64 t; cvta.to.shared.u64 t, %1; cvt.u32.u64 %0, t; }"
        : "=r"(a) : "l"(p));
    return a;
}
__device__ __forceinline__ void cp_async16(uint32_t smem_addr, const void* gptr) {
    asm volatile("cp.async.cg.shared.global [%0], [%1], 16;"
                 :: "r"(smem_addr), "l"(gptr) : "memory");
}
#define CP_ASYNC_COMMIT() asm volatile("cp.async.commit_group;" ::: "memory")
#define CP_ASYNC_WAIT_ALL() asm volatile("cp.async.wait_group 0;" ::: "memory")

// m16n8k16 fp16 MMA, fp32 accumulate (sm_70+ baseline PTX)
__device__ __forceinline__ void mma_f16(float c[4],
                                        uint32_t a0, uint32_t a1, uint32_t a2, uint32_t a3,
                                        uint32_t b0, uint32_t b1) {
    asm volatile(
        "mma.sync.aligned.m16n8k16.row.col.f32.f16.f16.f32 "
        "{%0,%1,%2,%3}, {%4,%5,%6,%7}, {%8,%9}, {%0,%1,%2,%3};"
        : "+f"(c[0]), "+f"(c[1]), "+f"(c[2]), "+f"(c[3])
        : "r"(a0), "r"(a1), "r"(a2), "r"(a3), "r"(b0), "r"(b1));
}

__device__ __forceinline__ uint32_t ldsm_u32(const __half* p) {
    return *reinterpret_cast<const uint32_t*>(p);
}

// ---------------------------------------------------------------------------
// Pre-pass 1: fp32 -> fp16 (x). 8 elems/thread.
// ---------------------------------------------------------------------------
__global__ void __launch_bounds__(256)
cvt_half(const float* __restrict__ in, __half* __restrict__ out) {
    size_t i = ((size_t)blockIdx.x * 256 + threadIdx.x) * 8;
    float4 v0 = *(const float4*)(in + i);
    float4 v1 = *(const float4*)(in + i + 4);
    __half2 h[4];
    h[0] = __floats2half2_rn(v0.x, v0.y);
    h[1] = __floats2half2_rn(v0.z, v0.w);
    h[2] = __floats2half2_rn(v1.x, v1.y);
    h[3] = __floats2half2_rn(v1.z, v1.w);
    *(uint4*)(out + i) = *reinterpret_cast<uint4*>(h);
}

// ---------------------------------------------------------------------------
// Pre-pass 2: transpose + fp16. in [R, Cc] fp32 -> out [Cc, R] fp16
// ---------------------------------------------------------------------------
__global__ void __launch_bounds__(256)
transpose_half(const float* __restrict__ in, __half* __restrict__ out,
               int R, int Cc) {
    __shared__ float tile[32][33];
    const int c0 = blockIdx.x * 32, r0 = blockIdx.y * 32;
    const int tx = threadIdx.x, ty = threadIdx.y;
    #pragma unroll
    for (int i = 0; i < 4; i++) {
        int r = ty + i * 8;
        tile[r][tx] = in[(size_t)(r0 + r) * Cc + c0 + tx];
    }
    __syncthreads();
    #pragma unroll
    for (int i = 0; i < 4; i++) {
        int c = ty + i * 8;
        out[(size_t)(c0 + c) * R + r0 + tx] = __float2half_rn(tile[tx][c]);
    }
}

// ---------------------------------------------------------------------------
// fp16 tensor GEMM: D[m][n] = sum_k A[m][k] * Bt[n][k], fp32 accumulate.
// BM=BN=128, BK=64, 256 threads (8 warps, 64x32 warp tiles), cp.async
// double-buffered. Tiles [row][72 halves] (stride 144B -> conflict-free frags).
// mode 0: out fp32 [m][n] = D + bias[n]
// mode 1: QKV scatter: Q (scaled) / K -> [B,H,T,HD] half; V -> [B,H,D,T] half
// ---------------------------------------------------------------------------
constexpr int GST = 72;                                  // halves per tile row
constexpr int GEMM_STAGE_BYTES = 2 * 128 * GST * 2;      // A+B = 36864
constexpr int GEMM_SMEM_BYTES  = 2 * GEMM_STAGE_BYTES;   // 73728
constexpr float QSCALE = 0.08838834764831845f;           // 128^-0.5

__global__ void __launch_bounds__(256, 2)
gemm_h(const __half* __restrict__ A, const __half* __restrict__ Bt,
       const float* __restrict__ bias, float* __restrict__ out,
       int K, int mode, int ldo) {
    extern __shared__ __half smh[];
    const uint32_t sb = smem_to_u32(smh);
    const int tid = threadIdx.x;
    const int wid = tid >> 5, lane = tid & 31;
    const int bm = blockIdx.y, bn = blockIdx.x;
    const int wm = (wid >> 2) * 64;
    const int wn = (wid & 3) * 32;
    const int fr = lane >> 2, tq = lane & 3;

    float acc[4][4][4];
    #pragma unroll
    for (int mi = 0; mi < 4; mi++)
        #pragma unroll
        for (int ni = 0; ni < 4; ni++)
            #pragma unroll
            for (int q = 0; q < 4; q++) acc[mi][ni][q] = 0.f;

    const __half* gA = A  + (size_t)bm * 128 * K;
    const __half* gB = Bt + (size_t)bn * 128 * K;

    // stage s: A at s*36864, B at +18432. Row r: 8 chunks of 16B (64 halves).
    auto load_stage = [&](int s, int k0) {
        const uint32_t base = sb + (uint32_t)s * GEMM_STAGE_BYTES;
        #pragma unroll
        for (int i = 0; i < 4; i++) {
            int u = i * 256 + tid;
            int r = u >> 3, c = u & 7;
            cp_async16(base + r * 144 + c * 16, gA + (size_t)r * K + k0 + c * 8);
        }
        #pragma unroll
        for (int i = 0; i < 4; i++) {
            int u = i * 256 + tid;
            int r = u >> 3, c = u & 7;
            cp_async16(base + 18432 + r * 144 + c * 16,
                       gB + (size_t)r * K + k0 + c * 8);
        }
    };

    load_stage(0, 0);
    CP_ASYNC_COMMIT();

    const int NT = K / 64;
    for (int j = 0; j < NT; j++) {
        CP_ASYNC_WAIT_ALL();
        __syncthreads();

        if (j + 1 < NT) {
            load_stage((j + 1) & 1, (j + 1) * 64);
            CP_ASYNC_COMMIT();
        }

        const __half* As = smh + (j & 1) * (GEMM_STAGE_BYTES / 2);
        const __half* Bs = As + 128 * GST;

        #pragma unroll
        for (int ks = 0; ks < 4; ks++) {
            const int kb = ks * 16 + tq * 2;
            uint32_t a[4][4], b[4][2];
            #pragma unroll
            for (int mi = 0; mi < 4; mi++) {
                int r = wm + mi * 16 + fr;
                a[mi][0] = ldsm_u32(As + r * GST + kb);
                a[mi][1] = ldsm_u32(As + (r + 8) * GST + kb);
                a[mi][2] = ldsm_u32(As + r * GST + kb + 8);
                a[mi][3] = ldsm_u32(As + (r + 8) * GST + kb + 8);
            }
            #pragma unroll
            for (int ni = 0; ni < 4; ni++) {
                int r = wn + ni * 8 + fr;
                b[ni][0] = ldsm_u32(Bs + r * GST + kb);
                b[ni][1] = ldsm_u32(Bs + r * GST + kb + 8);
            }
            #pragma unroll
            for (int mi = 0; mi < 4; mi++)
                #pragma unroll
                for (int ni = 0; ni < 4; ni++)
                    mma_f16(acc[mi][ni], a[mi][0], a[mi][1], a[mi][2], a[mi][3],
                            b[ni][0], b[ni][1]);
        }
        __syncthreads();
    }

    const int fc = tq * 2;

    if (mode == 1) {
        const int b  = bm >> 4;
        const int t0 = (bm & 15) * 128;
        const int n0g = bn * 128;
        const int s  = n0g >> 11;             // 0=Q 1=K 2=V
        const int h  = (n0g & 2047) >> 7;
        if (s == 2) {
            // V: write d-major [B,H,D,T]
            __half* base = g_Vt + (size_t)(b * H_ + h) * HD_ * T_;
            #pragma unroll
            for (int mi = 0; mi < 4; mi++) {
                #pragma unroll
                for (int ni = 0; ni < 4; ni++) {
                    int t = t0 + wm + mi * 16 + fr;
                    int n = wn + ni * 8 + fc;
                    base[(size_t)n * T_ + t]           = __float2half_rn(acc[mi][ni][0]);
                    base[(size_t)(n + 1) * T_ + t]     = __float2half_rn(acc[mi][ni][1]);
                    base[(size_t)n * T_ + t + 8]       = __float2half_rn(acc[mi][ni][2]);
                    base[(size_t)(n + 1) * T_ + t + 8] = __float2half_rn(acc[mi][ni][3]);
                }
            }
        } else {
            const float sc = (s == 0) ? QSCALE : 1.f;
            __half* base = ((s == 0) ? g_Qh : g_Kh)
                           + (size_t)(b * H_ + h) * T_ * HD_;
            #pragma unroll
            for (int mi = 0; mi < 4; mi++) {
                #pragma unroll
                for (int ni = 0; ni < 4; ni++) {
                    int t = t0 + wm + mi * 16 + fr;
                    int n = wn + ni * 8 + fc;
                    *(__half2*)(base + (size_t)t * HD_ + n) =
                        __floats2half2_rn(acc[mi][ni][0] * sc, acc[mi][ni][1] * sc);
                    *(__half2*)(base + (size_t)(t + 8) * HD_ + n) =
                        __floats2half2_rn(acc[mi][ni][2] * sc, acc[mi][ni][3] * sc);
                }
            }
        }
    } else {
        #pragma unroll
        for (int mi = 0; mi < 4; mi++) {
            #pragma unroll
            for (int ni = 0; ni < 4; ni++) {
                int m = bm * 128 + wm + mi * 16 + fr;
                int n = bn * 128 + wn + ni * 8 + fc;
                float b0 = bias[n], b1 = bias[n + 1];
                *(float2*)(out + (size_t)m * ldo + n) =
                    make_float2(acc[mi][ni][0] + b0, acc[mi][ni][1] + b1);
                *(float2*)(out + (size_t)(m + 8) * ldo + n) =
                    make_float2(acc[mi][ni][2] + b0, acc[mi][ni][3] + b1);
            }
        }
    }
}

// ---------------------------------------------------------------------------
// fp16 tensor-core flash attention, causal. Br=128, Bc=64, HD=128, 8 warps.
// Q pre-scaled fp16 [B,H,T,HD]; K fp16 [B,H,T,HD]; V fp16 d-major [B,H,D,T].
// Strides (halves): Q/K rows 136, Vt/Ps rows 72 -> conflict-free frag LDS.
// ---------------------------------------------------------------------------
constexpr int ASQ = 136;   // Qs/Ks row stride, halves
constexpr int ASV = 72;    // Vt/Ps row stride, halves
constexpr int ATTN_SMEM_BYTES =
    (128 * ASQ + 64 * ASQ + 128 * ASV + 128 * ASV) * 2;   // 89088 B

__global__ void __launch_bounds__(256, 2)
attn_h() {
    extern __shared__ __half smh[];
    __half* Qs = smh;
    __half* Ks = Qs + 128 * ASQ;
    __half* Vt = Ks + 64 * ASQ;
    __half* Ps = Vt + 128 * ASV;
    const uint32_t qs_b = smem_to_u32(Qs);
    const uint32_t ks_b = smem_to_u32(Ks);
    const uint32_t vt_b = smem_to_u32(Vt);

    const int tid = threadIdx.x;
    const int w = tid >> 5, lane = tid & 31;
    const int fr = lane >> 2, tq = lane & 3;
    const int qi = (T_ / 128 - 1) - blockIdx.x;    // heavy blocks first
    const int h = blockIdx.y, b = blockIdx.z;
    const int q0 = qi * 128;

    const __half* Qg = g_Qh + (size_t)(b * H_ + h) * T_ * HD_;
    const __half* Kg = g_Kh + (size_t)(b * H_ + h) * T_ * HD_;
    const __half* Vg = g_Vt + (size_t)(b * H_ + h) * HD_ * T_;

    // Q tile [128][128h]: 16 chunks/row
    #pragma unroll
    for (int i = 0; i < 8; i++) {
        int u = i * 256 + tid;
        int r = u >> 4, c = u & 15;
        cp_async16(qs_b + r * (ASQ * 2) + c * 16,
                   Qg + (size_t)(q0 + r) * HD_ + c * 8);
    }
    CP_ASYNC_COMMIT();

    const int qrow0 = q0 + w * 16 + fr;
    const int qrow1 = qrow0 + 8;

    float m0 = -1e30f, m1 = -1e30f, l0 = 0.f, l1 = 0.f;
    float o[16][4];
    #pragma unroll
    for (int nf = 0; nf < 16; nf++)
        #pragma unroll
        for (int q = 0; q < 4; q++) o[nf][q] = 0.f;

    const int nkt = 2 * qi + 2;
    for (int kt = 0; kt < nkt; kt++) {
        const int k0 = kt * 64;

        // K tile [64][128h], V tile [128 d][64h]
        #pragma unroll
        for (int i = 0; i < 4; i++) {
            int u = i * 256 + tid;
            int r = u >> 4, c = u & 15;
            cp_async16(ks_b + r * (ASQ * 2) + c * 16,
                       Kg + (size_t)(k0 + r) * HD_ + c * 8);
        }
        #pragma unroll
        for (int i = 0; i < 4; i++) {
            int u = i * 256 + tid;
            int r = u >> 3, c = u & 7;
            cp_async16(vt_b + r * (ASV * 2) + c * 16,
                       Vg + (size_t)r * T_ + k0 + c * 8);
        }
        CP_ASYNC_COMMIT();
        CP_ASYNC_WAIT_ALL();
        __syncthreads();

        // ---- S = Q K^T ----
        float s[8][4];
        #pragma unroll
        for (int nf = 0; nf < 8; nf++)
            #pragma unroll
            for (int q = 0; q < 4; q++) s[nf][q] = 0.f;

        #pragma unroll
        for (int ks = 0; ks < 8; ks++) {
            const int kb = ks * 16 + tq * 2;
            const int ra = w * 16 + fr;
            uint32_t a0 = ldsm_u32(Qs + ra * ASQ + kb);
            uint32_t a1 = ldsm_u32(Qs + (ra + 8) * ASQ + kb);
            uint32_t a2 = ldsm_u32(Qs + ra * ASQ + kb + 8);
            uint32_t a3 = ldsm_u32(Qs + (ra + 8) * ASQ + kb + 8);
            #pragma unroll
            for (int nf = 0; nf < 8; nf++) {
                const int rb = nf * 8 + fr;
                uint32_t b0 = ldsm_u32(Ks + rb * ASQ + kb);
                uint32_t b1 = ldsm_u32(Ks + rb * ASQ + kb + 8);
                mma_f16(s[nf], a0, a1, a2, a3, b0, b1);
            }
        }

        // ---- causal mask (last two k-tiles of this q-block) ----
        if (kt >= 2 * qi) {
            #pragma unroll
            for (int nf = 0; nf < 8; nf++) {
                int col = k0 + nf * 8 + 2 * tq;
                if (col     > qrow0) s[nf][0] = -1e30f;
                if (col + 1 > qrow0) s[nf][1] = -1e30f;
                if (col     > qrow1) s[nf][2] = -1e30f;
                if (col + 1 > qrow1) s[nf][3] = -1e30f;
            }
        }

        // ---- online softmax ----
        float mx0 = -1e30f, mx1 = -1e30f;
        #pragma unroll
        for (int nf = 0; nf < 8; nf++) {
            mx0 = fmaxf(mx0, fmaxf(s[nf][0], s[nf][1]));
            mx1 = fmaxf(mx1, fmaxf(s[nf][2], s[nf][3]));
        }
        mx0 = fmaxf(mx0, __shfl_xor_sync(0xffffffffu, mx0, 1));
        mx0 = fmaxf(mx0, __shfl_xor_sync(0xffffffffu, mx0, 2));
        mx1 = fmaxf(mx1, __shfl_xor_sync(0xffffffffu, mx1, 1));
        mx1 = fmaxf(mx1, __shfl_xor_sync(0xffffffffu, mx1, 2));

        float mn0 = fmaxf(m0, mx0), mn1 = fmaxf(m1, mx1);
        float al0 = __expf(m0 - mn0), al1 = __expf(m1 - mn1);

        float ps0 = 0.f, ps1 = 0.f;
        const int pr0 = (w * 16 + fr) * ASV;
        const int pr1 = pr0 + 8 * ASV;
        #pragma unroll
        for (int nf = 0; nf < 8; nf++) {
            float p0 = __expf(s[nf][0] - mn0);
            float p1 = __expf(s[nf][1] - mn0);
            float p2 = __expf(s[nf][2] - mn1);
            float p3 = __expf(s[nf][3] - mn1);
            ps0 += p0 + p1; ps1 += p2 + p3;
            int c = nf * 8 + 2 * tq;
            *(__half2*)(Ps + pr0 + c) = __floats2half2_rn(p0, p1);
            *(__half2*)(Ps + pr1 + c) = __floats2half2_rn(p2, p3);
        }
        ps0 += __shfl_xor_sync(0xffffffffu, ps0, 1);
        ps0 += __shfl_xor_sync(0xffffffffu, ps0, 2);
        ps1 += __shfl_xor_sync(0xffffffffu, ps1, 1);
        ps1 += __shfl_xor_sync(0xffffffffu, ps1, 2);
        l0 = l0 * al0 + ps0; m0 = mn0;
        l1 = l1 * al1 + ps1; m1 = mn1;

        #pragma unroll
        for (int nf = 0; nf < 16; nf++) {
            o[nf][0] *= al0; o[nf][1] *= al0;
            o[nf][2] *= al1; o[nf][3] *= al1;
        }

        __syncwarp();   // Ps rows warp-private: order STS->LDS within warp

        // ---- O += P V  (A = P [16 x 64], B = Vt rows d, cols k) ----
        #pragma unroll
        for (int ks = 0; ks < 4; ks++) {
            const int kb = ks * 16 + tq * 2;
            uint32_t a0 = ldsm_u32(Ps + pr0 + kb);
            uint32_t a1 = ldsm_u32(Ps + pr1 + kb);
            uint32_t a2 = ldsm_u32(Ps + pr0 + kb + 8);
            uint32_t a3 = ldsm_u32(Ps + pr1 + kb + 8);
            #pragma unroll
            for (int nf = 0; nf < 16; nf++) {
                const int rb = nf * 8 + fr;
                uint32_t b0 = ldsm_u32(Vt + rb * ASV + kb);
                uint32_t b1 = ldsm_u32(Vt + rb * ASV + kb + 8);
                mma_f16(o[nf], a0, a1, a2, a3, b0, b1);
            }
        }
        __syncthreads();   // before next tile overwrites Ks/Vt
    }

    // ---- epilogue: normalize, write fp16 Y (proj GEMM input) ----
    const float inv0 = 1.f / l0, inv1 = 1.f / l1;
    __half* y0 = g_Yh + (size_t)(b * T_ + qrow0) * C_ + h * HD_;
    __half* y1 = g_Yh + (size_t)(b * T_ + qrow1) * C_ + h * HD_;
    #pragma unroll
    for (int nf = 0; nf < 16; nf++) {
        int c = nf * 8 + 2 * tq;
        *(__half2*)(y0 + c) = __floats2half2_rn(o[nf][0] * inv0, o[nf][1] * inv0);
        *(__half2*)(y1 + c) = __floats2half2_rn(o[nf][2] * inv1, o[nf][3] * inv1);
    }
}

// ---------------------------------------------------------------------------
// Launch. Inputs (metadata order): x, mask, W_qkv, W_proj, b_proj
// ---------------------------------------------------------------------------
extern "C" void kernel_launch(void* const* d_in, const int* in_sizes, int n_in,
                              void* d_out, int out_size) {
    const float* x     = (const float*)d_in[0];
    const float* Wqkv  = (const float*)d_in[2];
    const float* Wproj = (const float*)d_in[3];
    const float* bproj = (const float*)d_in[4];
    float* out = (float*)d_out;

    static bool attr_set = false;
    if (!attr_set) {
        cudaFuncSetAttribute(attn_h,
                             cudaFuncAttributeMaxDynamicSharedMemorySize,
                             ATTN_SMEM_BYTES);
        cudaFuncSetAttribute(gemm_h,
                             cudaFuncAttributeMaxDynamicSharedMemorySize,
                             GEMM_SMEM_BYTES);
        attr_set = true;
    }

    __half* xh;  cudaGetSymbolAddress((void**)&xh,  g_xh);
    __half* wq;  cudaGetSymbolAddress((void**)&wq,  g_Wqkvh);
    __half* wp;  cudaGetSymbolAddress((void**)&wp,  g_Wprojh);
    __half* yh;  cudaGetSymbolAddress((void**)&yh,  g_Yh);

    // Pre-pass: fp16 conversion + weight transposes
    cvt_half<<<(M_ * C_) / 2048, 256>>>(x, xh);
    transpose_half<<<dim3(NQKV / 32, C_ / 32), dim3(32, 8)>>>(Wqkv, wq, C_, NQKV);
    transpose_half<<<dim3(C_ / 32, C_ / 32), dim3(32, 8)>>>(Wproj, wp, C_, C_);

    // QKV projection (fp16 tensor cores), scatter Q/K [B,H,T,HD], V [B,H,D,T]
    gemm_h<<<dim3(NQKV / 128, M_ / 128), 256, GEMM_SMEM_BYTES>>>(
        xh, wq, nullptr, nullptr, C_, 1, 0);

    // Attention (fp16 tensor-core flash, causal)
    attn_h<<<dim3(T_ / 128, H_, B_), 256, ATTN_SMEM_BYTES>>>();

    // Output projection (fp16 tensor cores) + fp32 bias
    gemm_h<<<dim3(C_ / 128, M_ / 128), 256, GEMM_SMEM_BYTES>>>(
        yh, wp, bproj, out, C_, 0, C_);
}

// round 6
// speedup vs baseline: 20.2052x; 1.0934x over previous
#include <cuda_runtime.h>
#include <cuda_fp16.h>
#include <math.h>
#include <cstdint>

// Problem constants
constexpr int B_ = 2, T_ = 2048, C_ = 2048, H_ = 16, HD_ = 128;
constexpr int M_ = B_ * T_;          // 4096
constexpr int NQKV = 3 * C_;         // 6144

// Scratch (allocation-free: __device__ globals), fp16 operands everywhere
__device__ __half g_Qh[(size_t)B_ * H_ * T_ * HD_];   // [B,H,T,HD], pre-scaled
__device__ __half g_Kh[(size_t)B_ * H_ * T_ * HD_];   // [B,H,T,HD]
__device__ __half g_Vt[(size_t)B_ * H_ * HD_ * T_];   // [B,H,D,T]  (d-major!)
__device__ __half g_Yh[(size_t)M_ * C_];              // attention out [M,C]
__device__ __half g_xh[(size_t)M_ * C_];              // x, fp16       [M,K]
__device__ __half g_Wqkvh[(size_t)NQKV * C_];         // Wqkv^T, fp16  [N,K]
__device__ __half g_Wprojh[(size_t)C_ * C_];          // Wproj^T, fp16 [N,K]

// ---------------------------------------------------------------------------
// Helpers
// ---------------------------------------------------------------------------
__device__ __forceinline__ uint32_t smem_to_u32(const void* p) {
    uint32_t a;
    asm("{ .reg .u64 t; cvta.to.shared.u64 t, %1; cvt.u32.u64 %0, t; }"
        : "=r"(a) : "l"(p));
    return a;
}
__device__ __forceinline__ void cp_async16(uint32_t smem_addr, const void* gptr) {
    asm volatile("cp.async.cg.shared.global [%0], [%1], 16;"
                 :: "r"(smem_addr), "l"(gptr) : "memory");
}
#define CP_ASYNC_COMMIT() asm volatile("cp.async.commit_group;" ::: "memory")
#define CP_ASYNC_WAIT_ALL() asm volatile("cp.async.wait_group 0;" ::: "memory")

// m16n8k16 fp16 MMA, fp32 accumulate (sm_70+ baseline PTX)
__device__ __forceinline__ void mma_f16(float c[4],
                                        uint32_t a0, uint32_t a1, uint32_t a2, uint32_t a3,
                                        uint32_t b0, uint32_t b1) {
    asm volatile(
        "mma.sync.aligned.m16n8k16.row.col.f32.f16.f16.f32 "
        "{%0,%1,%2,%3}, {%4,%5,%6,%7}, {%8,%9}, {%0,%1,%2,%3};"
        : "+f"(c[0]), "+f"(c[1]), "+f"(c[2]), "+f"(c[3])
        : "r"(a0), "r"(a1), "r"(a2), "r"(a3), "r"(b0), "r"(b1));
}

// ldmatrix x4: 4 8x8 b16 matrices; per-lane row addresses (sm_75+ baseline)
__device__ __forceinline__ void ldsm_x4(uint32_t& r0, uint32_t& r1,
                                        uint32_t& r2, uint32_t& r3, uint32_t addr) {
    asm volatile("ldmatrix.sync.aligned.m8n8.x4.shared.b16 {%0,%1,%2,%3}, [%4];"
                 : "=r"(r0), "=r"(r1), "=r"(r2), "=r"(r3) : "r"(addr));
}

// ---------------------------------------------------------------------------
// Pre-pass 1: fp32 -> fp16 (x). 8 elems/thread.
// ---------------------------------------------------------------------------
__global__ void __launch_bounds__(256)
cvt_half(const float* __restrict__ in, __half* __restrict__ out) {
    size_t i = ((size_t)blockIdx.x * 256 + threadIdx.x) * 8;
    float4 v0 = *(const float4*)(in + i);
    float4 v1 = *(const float4*)(in + i + 4);
    __half2 h[4];
    h[0] = __floats2half2_rn(v0.x, v0.y);
    h[1] = __floats2half2_rn(v0.z, v0.w);
    h[2] = __floats2half2_rn(v1.x, v1.y);
    h[3] = __floats2half2_rn(v1.z, v1.w);
    *(uint4*)(out + i) = *reinterpret_cast<uint4*>(h);
}

// ---------------------------------------------------------------------------
// Pre-pass 2: transpose + fp16. in [R, Cc] fp32 -> out [Cc, R] fp16
// ---------------------------------------------------------------------------
__global__ void __launch_bounds__(256)
transpose_half(const float* __restrict__ in, __half* __restrict__ out,
               int R, int Cc) {
    __shared__ float tile[32][33];
    const int c0 = blockIdx.x * 32, r0 = blockIdx.y * 32;
    const int tx = threadIdx.x, ty = threadIdx.y;
    #pragma unroll
    for (int i = 0; i < 4; i++) {
        int r = ty + i * 8;
        tile[r][tx] = in[(size_t)(r0 + r) * Cc + c0 + tx];
    }
    __syncthreads();
    #pragma unroll
    for (int i = 0; i < 4; i++) {
        int c = ty + i * 8;
        out[(size_t)(c0 + c) * R + r0 + tx] = __float2half_rn(tile[tx][c]);
    }
}

// ---------------------------------------------------------------------------
// fp16 tensor GEMM: D[m][n] = sum_k A[m][k] * Bt[n][k], fp32 accumulate.
// BM=BN=128, BK=64, 256 threads (8 warps, 64x32 warp tiles), cp.async
// double-buffered, ldmatrix fragment loads. Row stride 72 halves (144B:
// 8-row ldmatrix phases cover all 32 banks exactly once -> conflict-free).
// mode 0: out fp32 [m][n] = D + bias[n]
// mode 1: QKV scatter: Q (scaled) / K -> [B,H,T,HD] half; V -> [B,H,D,T] half
// ---------------------------------------------------------------------------
constexpr int GST = 72;                                  // halves per tile row
constexpr int GEMM_STAGE_BYTES = 2 * 128 * GST * 2;      // A+B = 36864
constexpr int GEMM_SMEM_BYTES  = 2 * GEMM_STAGE_BYTES;   // 73728
constexpr float QSCALE = 0.08838834764831845f;           // 128^-0.5

__global__ void __launch_bounds__(256, 2)
gemm_h(const __half* __restrict__ A, const __half* __restrict__ Bt,
       const float* __restrict__ bias, float* __restrict__ out,
       int K, int mode, int ldo) {
    extern __shared__ __half smh[];
    const uint32_t sb = smem_to_u32(smh);
    const int tid = threadIdx.x;
    const int wid = tid >> 5, lane = tid & 31;
    const int bm = blockIdx.y, bn = blockIdx.x;
    const int wm = (wid >> 2) * 64;
    const int wn = (wid & 3) * 32;
    const int fr = lane >> 2, tq = lane & 3;

    // ldmatrix per-lane offsets (bytes)
    // A (m16k16 x4): r0 lanes0-7 (m0-7,k0), r1 (m8-15,k0), r2 (m0-7,k8), r3 (m8-15,k8)
    const uint32_t aoff =
        (uint32_t)(((wm + (lane & 7) + ((lane >> 3) & 1) * 8) * GST
                    + ((lane >> 4) & 1) * 8) * 2);
    // B (n16k16 x4): r0 (n0-7,k0), r1 (n0-7,k8), r2 (n8-15,k0), r3 (n8-15,k8)
    const uint32_t boff =
        (uint32_t)(((wn + (lane & 7) + ((lane >> 4) & 1) * 8) * GST
                    + ((lane >> 3) & 1) * 8) * 2);

    float acc[4][4][4];
    #pragma unroll
    for (int mi = 0; mi < 4; mi++)
        #pragma unroll
        for (int ni = 0; ni < 4; ni++)
            #pragma unroll
            for (int q = 0; q < 4; q++) acc[mi][ni][q] = 0.f;

    const __half* gA = A  + (size_t)bm * 128 * K;
    const __half* gB = Bt + (size_t)bn * 128 * K;

    auto load_stage = [&](int s, int k0) {
        const uint32_t base = sb + (uint32_t)s * GEMM_STAGE_BYTES;
        #pragma unroll
        for (int i = 0; i < 4; i++) {
            int u = i * 256 + tid;
            int r = u >> 3, c = u & 7;
            cp_async16(base + r * 144 + c * 16, gA + (size_t)r * K + k0 + c * 8);
        }
        #pragma unroll
        for (int i = 0; i < 4; i++) {
            int u = i * 256 + tid;
            int r = u >> 3, c = u & 7;
            cp_async16(base + 18432 + r * 144 + c * 16,
                       gB + (size_t)r * K + k0 + c * 8);
        }
    };

    load_stage(0, 0);
    CP_ASYNC_COMMIT();

    const int NT = K / 64;
    for (int j = 0; j < NT; j++) {
        CP_ASYNC_WAIT_ALL();
        __syncthreads();

        if (j + 1 < NT) {
            load_stage((j + 1) & 1, (j + 1) * 64);
            CP_ASYNC_COMMIT();
        }

        const uint32_t As_u = sb + (uint32_t)(j & 1) * GEMM_STAGE_BYTES;
        const uint32_t Bs_u = As_u + 18432;

        #pragma unroll
        for (int ks = 0; ks < 4; ks++) {
            uint32_t a[4][4], bb[2][4];
            #pragma unroll
            for (int mi = 0; mi < 4; mi++)
                ldsm_x4(a[mi][0], a[mi][1], a[mi][2], a[mi][3],
                        As_u + aoff + (uint32_t)((mi * 16 * GST + ks * 16) * 2));
            #pragma unroll
            for (int nj = 0; nj < 2; nj++)
                ldsm_x4(bb[nj][0], bb[nj][1], bb[nj][2], bb[nj][3],
                        Bs_u + boff + (uint32_t)((nj * 16 * GST + ks * 16) * 2));
            #pragma unroll
            for (int mi = 0; mi < 4; mi++)
                #pragma unroll
                for (int ni = 0; ni < 4; ni++)
                    mma_f16(acc[mi][ni], a[mi][0], a[mi][1], a[mi][2], a[mi][3],
                            bb[ni >> 1][(ni & 1) * 2], bb[ni >> 1][(ni & 1) * 2 + 1]);
        }
        __syncthreads();
    }

    const int fc = tq * 2;

    if (mode == 1) {
        const int b  = bm >> 4;
        const int t0 = (bm & 15) * 128;
        const int n0g = bn * 128;
        const int s  = n0g >> 11;             // 0=Q 1=K 2=V
        const int h  = (n0g & 2047) >> 7;
        if (s == 2) {
            __half* base = g_Vt + (size_t)(b * H_ + h) * HD_ * T_;
            #pragma unroll
            for (int mi = 0; mi < 4; mi++) {
                #pragma unroll
                for (int ni = 0; ni < 4; ni++) {
                    int t = t0 + wm + mi * 16 + fr;
                    int n = wn + ni * 8 + fc;
                    base[(size_t)n * T_ + t]           = __float2half_rn(acc[mi][ni][0]);
                    base[(size_t)(n + 1) * T_ + t]     = __float2half_rn(acc[mi][ni][1]);
                    base[(size_t)n * T_ + t + 8]       = __float2half_rn(acc[mi][ni][2]);
                    base[(size_t)(n + 1) * T_ + t + 8] = __float2half_rn(acc[mi][ni][3]);
                }
            }
        } else {
            const float sc = (s == 0) ? QSCALE : 1.f;
            __half* base = ((s == 0) ? g_Qh : g_Kh)
                           + (size_t)(b * H_ + h) * T_ * HD_;
            #pragma unroll
            for (int mi = 0; mi < 4; mi++) {
                #pragma unroll
                for (int ni = 0; ni < 4; ni++) {
                    int t = t0 + wm + mi * 16 + fr;
                    int n = wn + ni * 8 + fc;
                    *(__half2*)(base + (size_t)t * HD_ + n) =
                        __floats2half2_rn(acc[mi][ni][0] * sc, acc[mi][ni][1] * sc);
                    *(__half2*)(base + (size_t)(t + 8) * HD_ + n) =
                        __floats2half2_rn(acc[mi][ni][2] * sc, acc[mi][ni][3] * sc);
                }
            }
        }
    } else {
        #pragma unroll
        for (int mi = 0; mi < 4; mi++) {
            #pragma unroll
            for (int ni = 0; ni < 4; ni++) {
                int m = bm * 128 + wm + mi * 16 + fr;
                int n = bn * 128 + wn + ni * 8 + fc;
                float b0 = bias[n], b1 = bias[n + 1];
                *(float2*)(out + (size_t)m * ldo + n) =
                    make_float2(acc[mi][ni][0] + b0, acc[mi][ni][1] + b1);
                *(float2*)(out + (size_t)(m + 8) * ldo + n) =
                    make_float2(acc[mi][ni][2] + b0, acc[mi][ni][3] + b1);
            }
        }
    }
}

// ---------------------------------------------------------------------------
// fp16 tensor-core flash attention, causal. Br=128, Bc=64, HD=128, 8 warps.
// Q pre-scaled fp16 [B,H,T,HD]; K fp16 [B,H,T,HD]; V fp16 d-major [B,H,D,T].
// ldmatrix fragment loads. Strides (halves): Q/K 136, Vt/Ps 72 (both 144B-ish
// class: stride mod 32 banks = 4 -> conflict-free ldmatrix phases).
// ---------------------------------------------------------------------------
constexpr int ASQ = 136;   // Qs/Ks row stride, halves
constexpr int ASV = 72;    // Vt/Ps row stride, halves
constexpr int ATTN_SMEM_BYTES =
    (128 * ASQ + 64 * ASQ + 128 * ASV + 128 * ASV) * 2;   // 89088 B

__global__ void __launch_bounds__(256, 2)
attn_h() {
    extern __shared__ __half smh[];
    __half* Qs = smh;
    __half* Ks = Qs + 128 * ASQ;
    __half* Vt = Ks + 64 * ASQ;
    __half* Ps = Vt + 128 * ASV;
    const uint32_t qs_b = smem_to_u32(Qs);
    const uint32_t ks_b = smem_to_u32(Ks);
    const uint32_t vt_b = smem_to_u32(Vt);
    const uint32_t ps_b = smem_to_u32(Ps);

    const int tid = threadIdx.x;
    const int w = tid >> 5, lane = tid & 31;
    const int fr = lane >> 2, tq = lane & 3;
    const int qi = (T_ / 128 - 1) - blockIdx.x;    // heavy blocks first
    const int h = blockIdx.y, b = blockIdx.z;
    const int q0 = qi * 128;

    const __half* Qg = g_Qh + (size_t)(b * H_ + h) * T_ * HD_;
    const __half* Kg = g_Kh + (size_t)(b * H_ + h) * T_ * HD_;
    const __half* Vg = g_Vt + (size_t)(b * H_ + h) * HD_ * T_;

    // ldmatrix per-lane offsets (bytes)
    const uint32_t a_row = (lane & 7) + ((lane >> 3) & 1) * 8;  // A-order
    const uint32_t a_col8 = ((lane >> 4) & 1) * 8;
    const uint32_t b_row = (lane & 7) + ((lane >> 4) & 1) * 8;  // B-order
    const uint32_t b_col8 = ((lane >> 3) & 1) * 8;
    const uint32_t q_off = (uint32_t)(((w * 16 + a_row) * ASQ + a_col8) * 2);
    const uint32_t k_off = (uint32_t)((b_row * ASQ + b_col8) * 2);
    const uint32_t p_off = (uint32_t)(((w * 16 + a_row) * ASV + a_col8) * 2);
    const uint32_t v_off = (uint32_t)((b_row * ASV + b_col8) * 2);

    // Q tile [128][128h]
    #pragma unroll
    for (int i = 0; i < 8; i++) {
        int u = i * 256 + tid;
        int r = u >> 4, c = u & 15;
        cp_async16(qs_b + r * (ASQ * 2) + c * 16,
                   Qg + (size_t)(q0 + r) * HD_ + c * 8);
    }
    CP_ASYNC_COMMIT();

    const int qrow0 = q0 + w * 16 + fr;
    const int qrow1 = qrow0 + 8;

    float m0 = -1e30f, m1 = -1e30f, l0 = 0.f, l1 = 0.f;
    float o[16][4];
    #pragma unroll
    for (int nf = 0; nf < 16; nf++)
        #pragma unroll
        for (int q = 0; q < 4; q++) o[nf][q] = 0.f;

    const int nkt = 2 * qi + 2;
    for (int kt = 0; kt < nkt; kt++) {
        const int k0 = kt * 64;

        // K tile [64][128h], V tile [128 d][64h]
        #pragma unroll
        for (int i = 0; i < 4; i++) {
            int u = i * 256 + tid;
            int r = u >> 4, c = u & 15;
            cp_async16(ks_b + r * (ASQ * 2) + c * 16,
                       Kg + (size_t)(k0 + r) * HD_ + c * 8);
        }
        #pragma unroll
        for (int i = 0; i < 4; i++) {
            int u = i * 256 + tid;
            int r = u >> 3, c = u & 7;
            cp_async16(vt_b + r * (ASV * 2) + c * 16,
                       Vg + (size_t)r * T_ + k0 + c * 8);
        }
        CP_ASYNC_COMMIT();
        CP_ASYNC_WAIT_ALL();
        __syncthreads();

        // ---- S = Q K^T ----
        float s[8][4];
        #pragma unroll
        for (int nf = 0; nf < 8; nf++)
            #pragma unroll
            for (int q = 0; q < 4; q++) s[nf][q] = 0.f;

        #pragma unroll
        for (int ks = 0; ks < 8; ks++) {
            uint32_t a0, a1, a2, a3, bb[4][4];
            ldsm_x4(a0, a1, a2, a3, qs_b + q_off + (uint32_t)(ks * 32));
            #pragma unroll
            for (int nj = 0; nj < 4; nj++)
                ldsm_x4(bb[nj][0], bb[nj][1], bb[nj][2], bb[nj][3],
                        ks_b + k_off + (uint32_t)((nj * 16 * ASQ) * 2 + ks * 32));
            #pragma unroll
            for (int nf = 0; nf < 8; nf++)
                mma_f16(s[nf], a0, a1, a2, a3,
                        bb[nf >> 1][(nf & 1) * 2], bb[nf >> 1][(nf & 1) * 2 + 1]);
        }

        // ---- causal mask (last two k-tiles of this q-block) ----
        if (kt >= 2 * qi) {
            #pragma unroll
            for (int nf = 0; nf < 8; nf++) {
                int col = k0 + nf * 8 + 2 * tq;
                if (col     > qrow0) s[nf][0] = -1e30f;
                if (col + 1 > qrow0) s[nf][1] = -1e30f;
                if (col     > qrow1) s[nf][2] = -1e30f;
                if (col + 1 > qrow1) s[nf][3] = -1e30f;
            }
        }

        // ---- online softmax ----
        float mx0 = -1e30f, mx1 = -1e30f;
        #pragma unroll
        for (int nf = 0; nf < 8; nf++) {
            mx0 = fmaxf(mx0, fmaxf(s[nf][0], s[nf][1]));
            mx1 = fmaxf(mx1, fmaxf(s[nf][2], s[nf][3]));
        }
        mx0 = fmaxf(mx0, __shfl_xor_sync(0xffffffffu, mx0, 1));
        mx0 = fmaxf(mx0, __shfl_xor_sync(0xffffffffu, mx0, 2));
        mx1 = fmaxf(mx1, __shfl_xor_sync(0xffffffffu, mx1, 1));
        mx1 = fmaxf(mx1, __shfl_xor_sync(0xffffffffu, mx1, 2));

        float mn0 = fmaxf(m0, mx0), mn1 = fmaxf(m1, mx1);
        float al0 = __expf(m0 - mn0), al1 = __expf(m1 - mn1);

        float ps0 = 0.f, ps1 = 0.f;
        const int pr0 = (w * 16 + fr) * ASV;
        const int pr1 = pr0 + 8 * ASV;
        #pragma unroll
        for (int nf = 0; nf < 8; nf++) {
            float p0 = __expf(s[nf][0] - mn0);
            float p1 = __expf(s[nf][1] - mn0);
            float p2 = __expf(s[nf][2] - mn1);
            float p3 = __expf(s[nf][3] - mn1);
            ps0 += p0 + p1; ps1 += p2 + p3;
            int c = nf * 8 + 2 * tq;
            *(__half2*)(Ps + pr0 + c) = __floats2half2_rn(p0, p1);
            *(__half2*)(Ps + pr1 + c) = __floats2half2_rn(p2, p3);
        }
        ps0 += __shfl_xor_sync(0xffffffffu, ps0, 1);
        ps0 += __shfl_xor_sync(0xffffffffu, ps0, 2);
        ps1 += __shfl_xor_sync(0xffffffffu, ps1, 1);
        ps1 += __shfl_xor_sync(0xffffffffu, ps1, 2);
        l0 = l0 * al0 + ps0; m0 = mn0;
        l1 = l1 * al1 + ps1; m1 = mn1;

        #pragma unroll
        for (int nf = 0; nf < 16; nf++) {
            o[nf][0] *= al0; o[nf][1] *= al0;
            o[nf][2] *= al1; o[nf][3] *= al1;
        }

        __syncwarp();   // Ps rows warp-private: order STS->LDS within warp

        // ---- O += P V  (A = P [16 x 64], B = Vt rows d, cols k) ----
        #pragma unroll
        for (int ks = 0; ks < 4; ks++) {
            uint32_t a0, a1, a2, a3, bb[8][4];
            ldsm_x4(a0, a1, a2, a3, ps_b + p_off + (uint32_t)(ks * 32));
            #pragma unroll
            for (int nj = 0; nj < 8; nj++)
                ldsm_x4(bb[nj][0], bb[nj][1], bb[nj][2], bb[nj][3],
                        vt_b + v_off + (uint32_t)((nj * 16 * ASV) * 2 + ks * 32));
            #pragma unroll
            for (int nf = 0; nf < 16; nf++)
                mma_f16(o[nf], a0, a1, a2, a3,
                        bb[nf >> 1][(nf & 1) * 2], bb[nf >> 1][(nf & 1) * 2 + 1]);
        }
        __syncthreads();   // before next tile overwrites Ks/Vt
    }

    // ---- epilogue: normalize, write fp16 Y (proj GEMM input) ----
    const float inv0 = 1.f / l0, inv1 = 1.f / l1;
    __half* y0 = g_Yh + (size_t)(b * T_ + qrow0) * C_ + h * HD_;
    __half* y1 = g_Yh + (size_t)(b * T_ + qrow1) * C_ + h * HD_;
    #pragma unroll
    for (int nf = 0; nf < 16; nf++) {
        int c = nf * 8 + 2 * tq;
        *(__half2*)(y0 + c) = __floats2half2_rn(o[nf][0] * inv0, o[nf][1] * inv0);
        *(__half2*)(y1 + c) = __floats2half2_rn(o[nf][2] * inv1, o[nf][3] * inv1);
    }
}

// ---------------------------------------------------------------------------
// Launch. Inputs (metadata order): x, mask, W_qkv, W_proj, b_proj
// ---------------------------------------------------------------------------
extern "C" void kernel_launch(void* const* d_in, const int* in_sizes, int n_in,
                              void* d_out, int out_size) {
    const float* x     = (const float*)d_in[0];
    const float* Wqkv  = (const float*)d_in[2];
    const float* Wproj = (const float*)d_in[3];
    const float* bproj = (const float*)d_in[4];
    float* out = (float*)d_out;

    static bool attr_set = false;
    if (!attr_set) {
        cudaFuncSetAttribute(attn_h,
                             cudaFuncAttributeMaxDynamicSharedMemorySize,
                             ATTN_SMEM_BYTES);
        cudaFuncSetAttribute(gemm_h,
                             cudaFuncAttributeMaxDynamicSharedMemorySize,
                             GEMM_SMEM_BYTES);
        attr_set = true;
    }

    __half* xh;  cudaGetSymbolAddress((void**)&xh,  g_xh);
    __half* wq;  cudaGetSymbolAddress((void**)&wq,  g_Wqkvh);
    __half* wp;  cudaGetSymbolAddress((void**)&wp,  g_Wprojh);
    __half* yh;  cudaGetSymbolAddress((void**)&yh,  g_Yh);

    // Pre-pass: fp16 conversion + weight transposes
    cvt_half<<<(M_ * C_) / 2048, 256>>>(x, xh);
    transpose_half<<<dim3(NQKV / 32, C_ / 32), dim3(32, 8)>>>(Wqkv, wq, C_, NQKV);
    transpose_half<<<dim3(C_ / 32, C_ / 32), dim3(32, 8)>>>(Wproj, wp, C_, C_);

    // QKV projection (fp16 tensor cores), scatter Q/K [B,H,T,HD], V [B,H,D,T]
    gemm_h<<<dim3(NQKV / 128, M_ / 128), 256, GEMM_SMEM_BYTES>>>(
        xh, wq, nullptr, nullptr, C_, 1, 0);

    // Attention (fp16 tensor-core flash, causal)
    attn_h<<<dim3(T_ / 128, H_, B_), 256, ATTN_SMEM_BYTES>>>();

    // Output projection (fp16 tensor cores) + fp32 bias
    gemm_h<<<dim3(C_ / 128, M_ / 128), 256, GEMM_SMEM_BYTES>>>(
        yh, wp, bproj, out, C_, 0, C_);
}

// round 8
// speedup vs baseline: 21.3903x; 1.0587x over previous
#include <cuda_runtime.h>
#include <cuda_fp16.h>
#include <math.h>
#include <cstdint>

// Problem constants
constexpr int B_ = 2, T_ = 2048, C_ = 2048, H_ = 16, HD_ = 128;
constexpr int M_ = B_ * T_;          // 4096
constexpr int NQKV = 3 * C_;         // 6144

// Scratch (allocation-free: __device__ globals), fp16 operands everywhere
__device__ __half g_Qh[(size_t)B_ * H_ * T_ * HD_];   // [B,H,T,HD], pre-scaled
__device__ __half g_Kh[(size_t)B_ * H_ * T_ * HD_];   // [B,H,T,HD]
__device__ __half g_Vh[(size_t)B_ * H_ * T_ * HD_];   // [B,H,T,HD] (t-major)
__device__ __half g_Yh[(size_t)M_ * C_];              // attention out [M,C]
__device__ __half g_xh[(size_t)M_ * C_];              // x, fp16       [M,K]
__device__ __half g_Wqkvh[(size_t)NQKV * C_];         // Wqkv^T, fp16  [N,K]
__device__ __half g_Wprojh[(size_t)C_ * C_];          // Wproj^T, fp16 [N,K]

// ---------------------------------------------------------------------------
// Helpers
// ---------------------------------------------------------------------------
__device__ __forceinline__ uint32_t smem_to_u32(const void* p) {
    uint32_t a;
    asm("{ .reg .u64 t; cvta.to.shared.u64 t, %1; cvt.u32.u64 %0, t; }"
        : "=r"(a) : "l"(p));
    return a;
}
__device__ __forceinline__ void cp_async16(uint32_t smem_addr, const void* gptr) {
    asm volatile("cp.async.cg.shared.global [%0], [%1], 16;"
                 :: "r"(smem_addr), "l"(gptr) : "memory");
}
#define CP_ASYNC_COMMIT() asm volatile("cp.async.commit_group;" ::: "memory")
#define CP_ASYNC_WAIT_ALL() asm volatile("cp.async.wait_group 0;" ::: "memory")
#define CP_ASYNC_WAIT_1()   asm volatile("cp.async.wait_group 1;" ::: "memory")

// m16n8k16 fp16 MMA, fp32 accumulate (sm_70+ baseline PTX)
__device__ __forceinline__ void mma_f16(float c[4],
                                        uint32_t a0, uint32_t a1, uint32_t a2, uint32_t a3,
                                        uint32_t b0, uint32_t b1) {
    asm volatile(
        "mma.sync.aligned.m16n8k16.row.col.f32.f16.f16.f32 "
        "{%0,%1,%2,%3}, {%4,%5,%6,%7}, {%8,%9}, {%0,%1,%2,%3};"
        : "+f"(c[0]), "+f"(c[1]), "+f"(c[2]), "+f"(c[3])
        : "r"(a0), "r"(a1), "r"(a2), "r"(a3), "r"(b0), "r"(b1));
}

__device__ __forceinline__ void ldsm_x4(uint32_t& r0, uint32_t& r1,
                                        uint32_t& r2, uint32_t& r3, uint32_t addr) {
    asm volatile("ldmatrix.sync.aligned.m8n8.x4.shared.b16 {%0,%1,%2,%3}, [%4];"
                 : "=r"(r0), "=r"(r1), "=r"(r2), "=r"(r3) : "r"(addr));
}
__device__ __forceinline__ void ldsm_x4_t(uint32_t& r0, uint32_t& r1,
                                          uint32_t& r2, uint32_t& r3, uint32_t addr) {
    asm volatile("ldmatrix.sync.aligned.m8n8.x4.trans.shared.b16 {%0,%1,%2,%3}, [%4];"
                 : "=r"(r0), "=r"(r1), "=r"(r2), "=r"(r3) : "r"(addr));
}

// ---------------------------------------------------------------------------
// Pre-pass 1: fp32 -> fp16 (x). 8 elems/thread.
// ---------------------------------------------------------------------------
__global__ void __launch_bounds__(256)
cvt_half(const float* __restrict__ in, __half* __restrict__ out) {
    size_t i = ((size_t)blockIdx.x * 256 + threadIdx.x) * 8;
    float4 v0 = *(const float4*)(in + i);
    float4 v1 = *(const float4*)(in + i + 4);
    __half2 h[4];
    h[0] = __floats2half2_rn(v0.x, v0.y);
    h[1] = __floats2half2_rn(v0.z, v0.w);
    h[2] = __floats2half2_rn(v1.x, v1.y);
    h[3] = __floats2half2_rn(v1.z, v1.w);
    *(uint4*)(out + i) = *reinterpret_cast<uint4*>(h);
}

// ---------------------------------------------------------------------------
// Pre-pass 2: transpose + fp16. in [R, Cc] fp32 -> out [Cc, R] fp16
// ---------------------------------------------------------------------------
__global__ void __launch_bounds__(256)
transpose_half(const float* __restrict__ in, __half* __restrict__ out,
               int R, int Cc) {
    __shared__ float tile[32][33];
    const int c0 = blockIdx.x * 32, r0 = blockIdx.y * 32;
    const int tx = threadIdx.x, ty = threadIdx.y;
    #pragma unroll
    for (int i = 0; i < 4; i++) {
        int r = ty + i * 8;
        tile[r][tx] = in[(size_t)(r0 + r) * Cc + c0 + tx];
    }
    __syncthreads();
    #pragma unroll
    for (int i = 0; i < 4; i++) {
        int c = ty + i * 8;
        out[(size_t)(c0 + c) * R + r0 + tx] = __float2half_rn(tile[tx][c]);
    }
}

// ---------------------------------------------------------------------------
// fp16 tensor GEMM: D[m][n] = sum_k A[m][k] * Bt[n][k], fp32 accumulate.
// BM=BN=128, BK=64, 256 threads (8 warps, 64x32 warp tiles).
// 3-stage cp.async ring, ONE __syncthreads per iter, ldmatrix fragments.
// mode 0: out fp32 [m][n] = D + bias[n]
// mode 1: QKV scatter: Q (scaled) / K / V -> [B,H,T,HD] half (coalesced)
// ---------------------------------------------------------------------------
constexpr int GST = 72;                                  // halves per tile row
constexpr int GEMM_STAGE_BYTES = 2 * 128 * GST * 2;      // A+B = 36864
constexpr int GEMM_SMEM_BYTES  = 3 * GEMM_STAGE_BYTES;   // 110592
constexpr float QSCALE = 0.08838834764831845f;           // 128^-0.5

__global__ void __launch_bounds__(256, 2)
gemm_h(const __half* __restrict__ A, const __half* __restrict__ Bt,
       const float* __restrict__ bias, float* __restrict__ out,
       int K, int mode, int ldo) {
    extern __shared__ __half smh[];
    const uint32_t sb = smem_to_u32(smh);
    const int tid = threadIdx.x;
    const int wid = tid >> 5, lane = tid & 31;
    const int bm = blockIdx.y, bn = blockIdx.x;
    const int wm = (wid >> 2) * 64;
    const int wn = (wid & 3) * 32;
    const int fr = lane >> 2, tq = lane & 3;

    // ldmatrix per-lane offsets (bytes)
    const uint32_t aoff =
        (uint32_t)(((wm + (lane & 7) + ((lane >> 3) & 1) * 8) * GST
                    + ((lane >> 4) & 1) * 8) * 2);
    const uint32_t boff =
        (uint32_t)(((wn + (lane & 7) + ((lane >> 4) & 1) * 8) * GST
                    + ((lane >> 3) & 1) * 8) * 2);

    float acc[4][4][4];
    #pragma unroll
    for (int mi = 0; mi < 4; mi++)
        #pragma unroll
        for (int ni = 0; ni < 4; ni++)
            #pragma unroll
            for (int q = 0; q < 4; q++) acc[mi][ni][q] = 0.f;

    const __half* gA = A  + (size_t)bm * 128 * K;
    const __half* gB = Bt + (size_t)bn * 128 * K;

    auto load_stage = [&](int s, int k0) {
        const uint32_t base = sb + (uint32_t)s * GEMM_STAGE_BYTES;
        #pragma unroll
        for (int i = 0; i < 4; i++) {
            int u = i * 256 + tid;
            int r = u >> 3, c = u & 7;
            cp_async16(base + r * 144 + c * 16, gA + (size_t)r * K + k0 + c * 8);
        }
        #pragma unroll
        for (int i = 0; i < 4; i++) {
            int u = i * 256 + tid;
            int r = u >> 3, c = u & 7;
            cp_async16(base + 18432 + r * 144 + c * 16,
                       gB + (size_t)r * K + k0 + c * 8);
        }
    };

    load_stage(0, 0);
    CP_ASYNC_COMMIT();
    load_stage(1, 64);
    CP_ASYNC_COMMIT();

    const int NT = K / 64;
    for (int j = 0; j < NT; j++) {
        CP_ASYNC_WAIT_1();          // stage j arrived
        __syncthreads();            // all warps finished stage j-1 compute
        if (j + 2 < NT)
            load_stage((j + 2) % 3, (j + 2) * 64);
        CP_ASYNC_COMMIT();          // (possibly empty group: keeps accounting)

        const uint32_t As_u = sb + (uint32_t)(j % 3) * GEMM_STAGE_BYTES;
        const uint32_t Bs_u = As_u + 18432;

        #pragma unroll
        for (int ks = 0; ks < 4; ks++) {
            uint32_t a[4][4], bb[2][4];
            #pragma unroll
            for (int mi = 0; mi < 4; mi++)
                ldsm_x4(a[mi][0], a[mi][1], a[mi][2], a[mi][3],
                        As_u + aoff + (uint32_t)((mi * 16 * GST + ks * 16) * 2));
            #pragma unroll
            for (int nj = 0; nj < 2; nj++)
                ldsm_x4(bb[nj][0], bb[nj][1], bb[nj][2], bb[nj][3],
                        Bs_u + boff + (uint32_t)((nj * 16 * GST + ks * 16) * 2));
            #pragma unroll
            for (int mi = 0; mi < 4; mi++)
                #pragma unroll
                for (int ni = 0; ni < 4; ni++)
                    mma_f16(acc[mi][ni], a[mi][0], a[mi][1], a[mi][2], a[mi][3],
                            bb[ni >> 1][(ni & 1) * 2], bb[ni >> 1][(ni & 1) * 2 + 1]);
        }
    }

    const int fc = tq * 2;

    if (mode == 1) {
        const int b  = bm >> 4;
        const int t0 = (bm & 15) * 128;
        const int n0g = bn * 128;
        const int s  = n0g >> 11;             // 0=Q 1=K 2=V
        const int h  = (n0g & 2047) >> 7;
        const float sc = (s == 0) ? QSCALE : 1.f;
        __half* base = ((s == 0) ? g_Qh : (s == 1) ? g_Kh : g_Vh)
                       + (size_t)(b * H_ + h) * T_ * HD_;
        #pragma unroll
        for (int mi = 0; mi < 4; mi++) {
            #pragma unroll
            for (int ni = 0; ni < 4; ni++) {
                int t = t0 + wm + mi * 16 + fr;
                int n = wn + ni * 8 + fc;
                *(__half2*)(base + (size_t)t * HD_ + n) =
                    __floats2half2_rn(acc[mi][ni][0] * sc, acc[mi][ni][1] * sc);
                *(__half2*)(base + (size_t)(t + 8) * HD_ + n) =
                    __floats2half2_rn(acc[mi][ni][2] * sc, acc[mi][ni][3] * sc);
            }
        }
    } else {
        #pragma unroll
        for (int mi = 0; mi < 4; mi++) {
            #pragma unroll
            for (int ni = 0; ni < 4; ni++) {
                int m = bm * 128 + wm + mi * 16 + fr;
                int n = bn * 128 + wn + ni * 8 + fc;
                float b0 = bias[n], b1 = bias[n + 1];
                *(float2*)(out + (size_t)m * ldo + n) =
                    make_float2(acc[mi][ni][0] + b0, acc[mi][ni][1] + b1);
                *(float2*)(out + (size_t)(m + 8) * ldo + n) =
                    make_float2(acc[mi][ni][2] + b0, acc[mi][ni][3] + b1);
            }
        }
    }
}

// ---------------------------------------------------------------------------
// fp16 tensor-core flash attention, causal. Br=128, Bc=64, HD=128, 8 warps.
// Q (pre-scaled), K, V all [B,H,T,HD] fp16. Double-buffered K/V tiles,
// ONE __syncthreads per k-tile. P kept in registers (S-frag == PV A-frag).
// V^T fragments via ldmatrix.trans from the t-major V tile.
// ---------------------------------------------------------------------------
constexpr int ASQ = 136;   // Q/K/V row stride, halves (272B: conflict-free)
constexpr int ATTN_SMEM_BYTES = (128 * ASQ + 4 * 64 * ASQ) * 2;   // 104448 B

__global__ void __launch_bounds__(256, 2)
attn_h() {
    extern __shared__ __half smh[];
    const uint32_t qs_b = smem_to_u32(smh);
    // layout (halves): Qs [0,17408) | Ks0 | Vs0 | Ks1 | Vs1 (each 64*136)
    const uint32_t kv_b[2][2] = {
        { qs_b + 17408u * 2, qs_b + 26112u * 2 },   // Ks0, Vs0
        { qs_b + 34816u * 2, qs_b + 43520u * 2 }    // Ks1, Vs1
    };

    const int tid = threadIdx.x;
    const int w = tid >> 5, lane = tid & 31;
    const int fr = lane >> 2, tq = lane & 3;
    const int qi = (T_ / 128 - 1) - blockIdx.x;    // heavy blocks first
    const int h = blockIdx.y, b = blockIdx.z;
    const int q0 = qi * 128;

    const __half* Qg = g_Qh + (size_t)(b * H_ + h) * T_ * HD_;
    const __half* Kg = g_Kh + (size_t)(b * H_ + h) * T_ * HD_;
    const __half* Vg = g_Vh + (size_t)(b * H_ + h) * T_ * HD_;

    // ldmatrix per-lane offsets (bytes)
    const uint32_t a_row = (lane & 7) + ((lane >> 3) & 1) * 8;  // A-operand order
    const uint32_t a_col8 = ((lane >> 4) & 1) * 8;
    const uint32_t b_row = (lane & 7) + ((lane >> 4) & 1) * 8;  // B-operand order
    const uint32_t b_col8 = ((lane >> 3) & 1) * 8;
    const uint32_t q_off = (uint32_t)(((w * 16 + a_row) * ASQ + a_col8) * 2);
    const uint32_t k_off = (uint32_t)((b_row * ASQ + b_col8) * 2);
    // V trans: matrices (t0..7,d0),(t8..15,d0),(t0..7,d8),(t8..15,d8)
    const uint32_t v_off = (uint32_t)((a_row * ASQ + a_col8) * 2);

    auto load_kv = [&](int buf, int k0) {
        #pragma unroll
        for (int i = 0; i < 4; i++) {
            int u = i * 256 + tid;
            int r = u >> 4, c = u & 15;
            cp_async16(kv_b[buf][0] + r * (ASQ * 2) + c * 16,
                       Kg + (size_t)(k0 + r) * HD_ + c * 8);
        }
        #pragma unroll
        for (int i = 0; i < 4; i++) {
            int u = i * 256 + tid;
            int r = u >> 4, c = u & 15;
            cp_async16(kv_b[buf][1] + r * (ASQ * 2) + c * 16,
                       Vg + (size_t)(k0 + r) * HD_ + c * 8);
        }
    };

    // Prologue: Q tile + KV(0) in one group
    #pragma unroll
    for (int i = 0; i < 8; i++) {
        int u = i * 256 + tid;
        int r = u >> 4, c = u & 15;
        cp_async16(qs_b + r * (ASQ * 2) + c * 16,
                   Qg + (size_t)(q0 + r) * HD_ + c * 8);
    }
    load_kv(0, 0);
    CP_ASYNC_COMMIT();

    const int qrow0 = q0 + w * 16 + fr;
    const int qrow1 = qrow0 + 8;

    float m0 = -1e30f, m1 = -1e30f, l0 = 0.f, l1 = 0.f;
    float o[16][4];
    #pragma unroll
    for (int nf = 0; nf < 16; nf++)
        #pragma unroll
        for (int q = 0; q < 4; q++) o[nf][q] = 0.f;

    const int nkt = 2 * qi + 2;
    for (int kt = 0; kt < nkt; kt++) {
        const int k0 = kt * 64;
        const uint32_t ks_u = kv_b[kt & 1][0];
        const uint32_t vs_u = kv_b[kt & 1][1];

        CP_ASYNC_WAIT_ALL();        // KV(kt) (and Q on kt=0) arrived
        __syncthreads();            // all warps done with buffer (kt-1)&1
        if (kt + 1 < nkt)
            load_kv((kt + 1) & 1, k0 + 64);
        CP_ASYNC_COMMIT();

        // ---- S = Q K^T ----
        float s[8][4];
        #pragma unroll
        for (int nf = 0; nf < 8; nf++)
            #pragma unroll
            for (int q = 0; q < 4; q++) s[nf][q] = 0.f;

        #pragma unroll
        for (int ks = 0; ks < 8; ks++) {
            uint32_t a0, a1, a2, a3, bb[4][4];
            ldsm_x4(a0, a1, a2, a3, qs_b + q_off + (uint32_t)(ks * 32));
            #pragma unroll
            for (int nj = 0; nj < 4; nj++)
                ldsm_x4(bb[nj][0], bb[nj][1], bb[nj][2], bb[nj][3],
                        ks_u + k_off + (uint32_t)((nj * 16 * ASQ) * 2 + ks * 32));
            #pragma unroll
            for (int nf = 0; nf < 8; nf++)
                mma_f16(s[nf], a0, a1, a2, a3,
                        bb[nf >> 1][(nf & 1) * 2], bb[nf >> 1][(nf & 1) * 2 + 1]);
        }

        // ---- causal mask (last two k-tiles of this q-block) ----
        if (kt >= 2 * qi) {
            #pragma unroll
            for (int nf = 0; nf < 8; nf++) {
                int col = k0 + nf * 8 + 2 * tq;
                if (col     > qrow0) s[nf][0] = -1e30f;
                if (col + 1 > qrow0) s[nf][1] = -1e30f;
                if (col     > qrow1) s[nf][2] = -1e30f;
                if (col + 1 > qrow1) s[nf][3] = -1e30f;
            }
        }

        // ---- online softmax ----
        float mx0 = -1e30f, mx1 = -1e30f;
        #pragma unroll
        for (int nf = 0; nf < 8; nf++) {
            mx0 = fmaxf(mx0, fmaxf(s[nf][0], s[nf][1]));
            mx1 = fmaxf(mx1, fmaxf(s[nf][2], s[nf][3]));
        }
        mx0 = fmaxf(mx0, __shfl_xor_sync(0xffffffffu, mx0, 1));
        mx0 = fmaxf(mx0, __shfl_xor_sync(0xffffffffu, mx0, 2));
        mx1 = fmaxf(mx1, __shfl_xor_sync(0xffffffffu, mx1, 1));
        mx1 = fmaxf(mx1, __shfl_xor_sync(0xffffffffu, mx1, 2));

        float mn0 = fmaxf(m0, mx0), mn1 = fmaxf(m1, mx1);
        float al0 = __expf(m0 - mn0), al1 = __expf(m1 - mn1);

        // exp + pack P into A-fragment registers (no smem round-trip)
        uint32_t pa[4][4];
        float ps0 = 0.f, ps1 = 0.f;
        #pragma unroll
        for (int nf = 0; nf < 8; nf++) {
            float p0 = __expf(s[nf][0] - mn0);
            float p1 = __expf(s[nf][1] - mn0);
            float p2 = __expf(s[nf][2] - mn1);
            float p3 = __expf(s[nf][3] - mn1);
            ps0 += p0 + p1; ps1 += p2 + p3;
            const int ks2 = nf >> 1, lo = (nf & 1) * 2;
            __half2 h01 = __floats2half2_rn(p0, p1);
            __half2 h23 = __floats2half2_rn(p2, p3);
            pa[ks2][lo]     = *reinterpret_cast<uint32_t*>(&h01);
            pa[ks2][lo + 1] = *reinterpret_cast<uint32_t*>(&h23);
        }
        ps0 += __shfl_xor_sync(0xffffffffu, ps0, 1);
        ps0 += __shfl_xor_sync(0xffffffffu, ps0, 2);
        ps1 += __shfl_xor_sync(0xffffffffu, ps1, 1);
        ps1 += __shfl_xor_sync(0xffffffffu, ps1, 2);
        l0 = l0 * al0 + ps0; m0 = mn0;
        l1 = l1 * al1 + ps1; m1 = mn1;

        #pragma unroll
        for (int nf = 0; nf < 16; nf++) {
            o[nf][0] *= al0; o[nf][1] *= al0;
            o[nf][2] *= al1; o[nf][3] *= al1;
        }

        // ---- O += P V : B-frags = ldmatrix.trans of V[t][d] ----
        // nj covers d-tiles of 16 (8 tiles -> full HD=128)
        #pragma unroll
        for (int ks2 = 0; ks2 < 4; ks2++) {
            #pragma unroll
            for (int nj = 0; nj < 8; nj++) {
                uint32_t r0, r1, r2, r3;
                ldsm_x4_t(r0, r1, r2, r3,
                          vs_u + v_off +
                          (uint32_t)((ks2 * 16 * ASQ + nj * 16) * 2));
                mma_f16(o[nj * 2],     pa[ks2][0], pa[ks2][1], pa[ks2][2], pa[ks2][3], r0, r1);
                mma_f16(o[nj * 2 + 1], pa[ks2][0], pa[ks2][1], pa[ks2][2], pa[ks2][3], r2, r3);
            }
        }
    }

    // ---- epilogue: normalize, write fp16 Y (proj GEMM input) ----
    const float inv0 = 1.f / l0, inv1 = 1.f / l1;
    __half* y0 = g_Yh + (size_t)(b * T_ + qrow0) * C_ + h * HD_;
    __half* y1 = g_Yh + (size_t)(b * T_ + qrow1) * C_ + h * HD_;
    #pragma unroll
    for (int nf = 0; nf < 16; nf++) {
        int c = nf * 8 + 2 * tq;
        *(__half2*)(y0 + c) = __floats2half2_rn(o[nf][0] * inv0, o[nf][1] * inv0);
        *(__half2*)(y1 + c) = __floats2half2_rn(o[nf][2] * inv1, o[nf][3] * inv1);
    }
}

// ---------------------------------------------------------------------------
// Launch. Inputs (metadata order): x, mask, W_qkv, W_proj, b_proj
// ---------------------------------------------------------------------------
extern "C" void kernel_launch(void* const* d_in, const int* in_sizes, int n_in,
                              void* d_out, int out_size) {
    const float* x     = (const float*)d_in[0];
    const float* Wqkv  = (const float*)d_in[2];
    const float* Wproj = (const float*)d_in[3];
    const float* bproj = (const float*)d_in[4];
    float* out = (float*)d_out;

    static bool attr_set = false;
    if (!attr_set) {
        cudaFuncSetAttribute(attn_h,
                             cudaFuncAttributeMaxDynamicSharedMemorySize,
                             ATTN_SMEM_BYTES);
        cudaFuncSetAttribute(gemm_h,
                             cudaFuncAttributeMaxDynamicSharedMemorySize,
                             GEMM_SMEM_BYTES);
        attr_set = true;
    }

    __half* xh;  cudaGetSymbolAddress((void**)&xh,  g_xh);
    __half* wq;  cudaGetSymbolAddress((void**)&wq,  g_Wqkvh);
    __half* wp;  cudaGetSymbolAddress((void**)&wp,  g_Wprojh);
    __half* yh;  cudaGetSymbolAddress((void**)&yh,  g_Yh);

    // Pre-pass: fp16 conversion + weight transposes
    cvt_half<<<(M_ * C_) / 2048, 256>>>(x, xh);
    transpose_half<<<dim3(NQKV / 32, C_ / 32), dim3(32, 8)>>>(Wqkv, wq, C_, NQKV);
    transpose_half<<<dim3(C_ / 32, C_ / 32), dim3(32, 8)>>>(Wproj, wp, C_, C_);

    // QKV projection (fp16 tensor cores), scatter Q/K/V -> [B,H,T,HD]
    gemm_h<<<dim3(NQKV / 128, M_ / 128), 256, GEMM_SMEM_BYTES>>>(
        xh, wq, nullptr, nullptr, C_, 1, 0);

    // Attention (fp16 tensor-core flash, causal)
    attn_h<<<dim3(T_ / 128, H_, B_), 256, ATTN_SMEM_BYTES>>>();

    // Output projection (fp16 tensor cores) + fp32 bias
    gemm_h<<<dim3(C_ / 128, M_ / 128), 256, GEMM_SMEM_BYTES>>>(
        yh, wp, bproj, out, C_, 0, C_);
}

// round 9
// speedup vs baseline: 21.6863x; 1.0138x over previous
#include <cuda_runtime.h>
#include <cuda_fp16.h>
#include <math.h>
#include <cstdint>

// Problem constants
constexpr int B_ = 2, T_ = 2048, C_ = 2048, H_ = 16, HD_ = 128;
constexpr int M_ = B_ * T_;          // 4096
constexpr int NQKV = 3 * C_;         // 6144

// Scratch (allocation-free: __device__ globals), fp16 operands everywhere
__device__ __half g_Qh[(size_t)B_ * H_ * T_ * HD_];   // [B,H,T,HD], pre-scaled
__device__ __half g_Kh[(size_t)B_ * H_ * T_ * HD_];   // [B,H,T,HD]
__device__ __half g_Vh[(size_t)B_ * H_ * T_ * HD_];   // [B,H,T,HD] (t-major)
__device__ __half g_Yh[(size_t)M_ * C_];              // attention out [M,C]
__device__ __half g_xh[(size_t)M_ * C_];              // x fp16        [M,K]
__device__ __half g_Wqkvh[(size_t)C_ * NQKV];         // Wqkv fp16     [K,N] native
__device__ __half g_Wprojh[(size_t)C_ * C_];          // Wproj fp16    [K,N] native

// ---------------------------------------------------------------------------
// Helpers
// ---------------------------------------------------------------------------
__device__ __forceinline__ uint32_t smem_to_u32(const void* p) {
    uint32_t a;
    asm("{ .reg .u64 t; cvta.to.shared.u64 t, %1; cvt.u32.u64 %0, t; }"
        : "=r"(a) : "l"(p));
    return a;
}
__device__ __forceinline__ void cp_async16(uint32_t smem_addr, const void* gptr) {
    asm volatile("cp.async.cg.shared.global [%0], [%1], 16;"
                 :: "r"(smem_addr), "l"(gptr) : "memory");
}
#define CP_ASYNC_COMMIT() asm volatile("cp.async.commit_group;" ::: "memory")
#define CP_ASYNC_WAIT_ALL() asm volatile("cp.async.wait_group 0;" ::: "memory")
#define CP_ASYNC_WAIT_1()   asm volatile("cp.async.wait_group 1;" ::: "memory")

// m16n8k16 fp16 MMA, fp32 accumulate (sm_70+ baseline PTX)
__device__ __forceinline__ void mma_f16(float c[4],
                                        uint32_t a0, uint32_t a1, uint32_t a2, uint32_t a3,
                                        uint32_t b0, uint32_t b1) {
    asm volatile(
        "mma.sync.aligned.m16n8k16.row.col.f32.f16.f16.f32 "
        "{%0,%1,%2,%3}, {%4,%5,%6,%7}, {%8,%9}, {%0,%1,%2,%3};"
        : "+f"(c[0]), "+f"(c[1]), "+f"(c[2]), "+f"(c[3])
        : "r"(a0), "r"(a1), "r"(a2), "r"(a3), "r"(b0), "r"(b1));
}

__device__ __forceinline__ void ldsm_x4(uint32_t& r0, uint32_t& r1,
                                        uint32_t& r2, uint32_t& r3, uint32_t addr) {
    asm volatile("ldmatrix.sync.aligned.m8n8.x4.shared.b16 {%0,%1,%2,%3}, [%4];"
                 : "=r"(r0), "=r"(r1), "=r"(r2), "=r"(r3) : "r"(addr));
}
__device__ __forceinline__ void ldsm_x4_t(uint32_t& r0, uint32_t& r1,
                                          uint32_t& r2, uint32_t& r3, uint32_t addr) {
    asm volatile("ldmatrix.sync.aligned.m8n8.x4.trans.shared.b16 {%0,%1,%2,%3}, [%4];"
                 : "=r"(r0), "=r"(r1), "=r"(r2), "=r"(r3) : "r"(addr));
}

// ---------------------------------------------------------------------------
// Fused pre-pass: one launch converts x, W_qkv, W_proj fp32 -> fp16 (no
// transposes needed anymore -- GEMM consumes W in native [K,N] layout).
// ---------------------------------------------------------------------------
constexpr size_t NX  = (size_t)M_ * C_;        //  8,388,608
constexpr size_t NWQ = (size_t)C_ * NQKV;      // 12,582,912
constexpr size_t NWP = (size_t)C_ * C_;        //  4,194,304
constexpr size_t NTOT = NX + NWQ + NWP;        // 25,165,824 (mult of 8)

__global__ void __launch_bounds__(256)
cvt_all(const float* __restrict__ x, const float* __restrict__ wqkv,
        const float* __restrict__ wproj) {
    size_t i = ((size_t)blockIdx.x * 256 + threadIdx.x) * 8;
    const float* src;
    __half* dst;
    size_t off;
    if (i < NX)            { src = x;     dst = g_xh;     off = i; }
    else if (i < NX + NWQ) { src = wqkv;  dst = g_Wqkvh;  off = i - NX; }
    else                   { src = wproj; dst = g_Wprojh; off = i - NX - NWQ; }
    float4 v0 = *(const float4*)(src + off);
    float4 v1 = *(const float4*)(src + off + 4);
    __half2 h[4];
    h[0] = __floats2half2_rn(v0.x, v0.y);
    h[1] = __floats2half2_rn(v0.z, v0.w);
    h[2] = __floats2half2_rn(v1.x, v1.y);
    h[3] = __floats2half2_rn(v1.z, v1.w);
    *(uint4*)(dst + off) = *reinterpret_cast<uint4*>(h);
}

// ---------------------------------------------------------------------------
// fp16 tensor GEMM: D[m][n] = sum_k A[m][k] * Bw[k][n], fp32 accumulate.
// A row-major [M,K]; B in NATIVE [K,N] layout (fragments via ldmatrix.trans,
// banking proven conflict-free by the attention PV path).
// BM=BN=128, BK=64, 256 threads (8 warps, 64x32 warp tiles),
// 3-stage cp.async ring, one __syncthreads per iter.
// mode 0: out fp32 [m][n] = D + bias[n]
// mode 1: QKV scatter: Q (scaled) / K / V -> [B,H,T,HD] half (coalesced)
// ---------------------------------------------------------------------------
constexpr int AST = 72;    // A tile row stride (halves): 64 + 8 pad
constexpr int BST = 136;   // B tile row stride (halves): 128 + 8 pad
constexpr int A_STAGE = 128 * AST * 2;            // 18432 B
constexpr int B_STAGE = 64 * BST * 2;             // 17408 B
constexpr int GEMM_STAGE_BYTES = A_STAGE + B_STAGE;   // 35840
constexpr int GEMM_SMEM_BYTES  = 3 * GEMM_STAGE_BYTES; // 107520
constexpr float QSCALE = 0.08838834764831845f;    // 128^-0.5

__global__ void __launch_bounds__(256, 2)
gemm_h(const __half* __restrict__ A, const __half* __restrict__ Bw,
       const float* __restrict__ bias, float* __restrict__ out,
       int K, int ldB, int mode, int ldo) {
    extern __shared__ __half smh[];
    const uint32_t sb = smem_to_u32(smh);
    const int tid = threadIdx.x;
    const int wid = tid >> 5, lane = tid & 31;
    const int bm = blockIdx.y, bn = blockIdx.x;
    const int wm = (wid >> 2) * 64;
    const int wn = (wid & 3) * 32;
    const int fr = lane >> 2, tq = lane & 3;

    // A ldmatrix (non-trans) per-lane offset (bytes)
    const uint32_t aoff =
        (uint32_t)(((wm + (lane & 7) + ((lane >> 3) & 1) * 8) * AST
                    + ((lane >> 4) & 1) * 8) * 2);
    // B trans-ldmatrix per-lane offset (halves; rows = k, cols = n)
    const uint32_t btoff =
        (uint32_t)(((lane & 7) + ((lane >> 3) & 1) * 8) * BST
                   + ((lane >> 4) & 1) * 8);

    float acc[4][4][4];
    #pragma unroll
    for (int mi = 0; mi < 4; mi++)
        #pragma unroll
        for (int ni = 0; ni < 4; ni++)
            #pragma unroll
            for (int q = 0; q < 4; q++) acc[mi][ni][q] = 0.f;

    const __half* gA = A  + (size_t)bm * 128 * K;
    const __half* gB = Bw + (size_t)bn * 128;     // column block; rows advance k

    auto load_stage = [&](int s, int k0) {
        const uint32_t base = sb + (uint32_t)s * GEMM_STAGE_BYTES;
        // A: 128 rows x 64 halves
        #pragma unroll
        for (int i = 0; i < 4; i++) {
            int u = i * 256 + tid;
            int r = u >> 3, c = u & 7;
            cp_async16(base + r * (AST * 2) + c * 16,
                       gA + (size_t)r * K + k0 + c * 8);
        }
        // B: 64 k-rows x 128 n-halves (fully coalesced along n)
        #pragma unroll
        for (int i = 0; i < 4; i++) {
            int u = i * 256 + tid;
            int r = u >> 4, c = u & 15;
            cp_async16(base + A_STAGE + r * (BST * 2) + c * 16,
                       gB + (size_t)(k0 + r) * ldB + c * 8);
        }
    };

    load_stage(0, 0);
    CP_ASYNC_COMMIT();
    load_stage(1, 64);
    CP_ASYNC_COMMIT();

    const int NT = K / 64;
    for (int j = 0; j < NT; j++) {
        CP_ASYNC_WAIT_1();          // stage j arrived
        __syncthreads();            // all warps finished stage j-1 compute
        if (j + 2 < NT)
            load_stage((j + 2) % 3, (j + 2) * 64);
        CP_ASYNC_COMMIT();

        const uint32_t As_u = sb + (uint32_t)(j % 3) * GEMM_STAGE_BYTES;
        const uint32_t Bs_u = As_u + A_STAGE;

        #pragma unroll
        for (int ks = 0; ks < 4; ks++) {
            uint32_t a[4][4], bb[2][4];
            #pragma unroll
            for (int mi = 0; mi < 4; mi++)
                ldsm_x4(a[mi][0], a[mi][1], a[mi][2], a[mi][3],
                        As_u + aoff + (uint32_t)((mi * 16 * AST + ks * 16) * 2));
            #pragma unroll
            for (int nj = 0; nj < 2; nj++)
                ldsm_x4_t(bb[nj][0], bb[nj][1], bb[nj][2], bb[nj][3],
                          Bs_u + (uint32_t)((btoff + ks * 16 * BST
                                             + wn + nj * 16) * 2));
            #pragma unroll
            for (int mi = 0; mi < 4; mi++)
                #pragma unroll
                for (int ni = 0; ni < 4; ni++)
                    mma_f16(acc[mi][ni], a[mi][0], a[mi][1], a[mi][2], a[mi][3],
                            bb[ni >> 1][(ni & 1) * 2], bb[ni >> 1][(ni & 1) * 2 + 1]);
        }
    }

    const int fc = tq * 2;

    if (mode == 1) {
        const int b  = bm >> 4;
        const int t0 = (bm & 15) * 128;
        const int n0g = bn * 128;
        const int s  = n0g >> 11;             // 0=Q 1=K 2=V
        const int h  = (n0g & 2047) >> 7;
        const float sc = (s == 0) ? QSCALE : 1.f;
        __half* base = ((s == 0) ? g_Qh : (s == 1) ? g_Kh : g_Vh)
                       + (size_t)(b * H_ + h) * T_ * HD_;
        #pragma unroll
        for (int mi = 0; mi < 4; mi++) {
            #pragma unroll
            for (int ni = 0; ni < 4; ni++) {
                int t = t0 + wm + mi * 16 + fr;
                int n = wn + ni * 8 + fc;
                *(__half2*)(base + (size_t)t * HD_ + n) =
                    __floats2half2_rn(acc[mi][ni][0] * sc, acc[mi][ni][1] * sc);
                *(__half2*)(base + (size_t)(t + 8) * HD_ + n) =
                    __floats2half2_rn(acc[mi][ni][2] * sc, acc[mi][ni][3] * sc);
            }
        }
    } else {
        #pragma unroll
        for (int mi = 0; mi < 4; mi++) {
            #pragma unroll
            for (int ni = 0; ni < 4; ni++) {
                int m = bm * 128 + wm + mi * 16 + fr;
                int n = bn * 128 + wn + ni * 8 + fc;
                float b0 = bias[n], b1 = bias[n + 1];
                *(float2*)(out + (size_t)m * ldo + n) =
                    make_float2(acc[mi][ni][0] + b0, acc[mi][ni][1] + b1);
                *(float2*)(out + (size_t)(m + 8) * ldo + n) =
                    make_float2(acc[mi][ni][2] + b0, acc[mi][ni][3] + b1);
            }
        }
    }
}

// ---------------------------------------------------------------------------
// fp16 tensor-core flash attention, causal. Br=128, Bc=64, HD=128, 8 warps.
// Q (pre-scaled), K, V all [B,H,T,HD] fp16. Double-buffered K/V tiles,
// ONE __syncthreads per k-tile. P kept in registers (S-frag == PV A-frag).
// V^T fragments via ldmatrix.trans from the t-major V tile. (R8, proven)
// ---------------------------------------------------------------------------
constexpr int ASQ = 136;   // Q/K/V row stride, halves (272B: conflict-free)
constexpr int ATTN_SMEM_BYTES = (128 * ASQ + 4 * 64 * ASQ) * 2;   // 104448 B

__global__ void __launch_bounds__(256, 2)
attn_h() {
    extern __shared__ __half smh[];
    const uint32_t qs_b = smem_to_u32(smh);
    const uint32_t kv_b[2][2] = {
        { qs_b + 17408u * 2, qs_b + 26112u * 2 },   // Ks0, Vs0
        { qs_b + 34816u * 2, qs_b + 43520u * 2 }    // Ks1, Vs1
    };

    const int tid = threadIdx.x;
    const int w = tid >> 5, lane = tid & 31;
    const int fr = lane >> 2, tq = lane & 3;
    const int qi = (T_ / 128 - 1) - blockIdx.x;    // heavy blocks first
    const int h = blockIdx.y, b = blockIdx.z;
    const int q0 = qi * 128;

    const __half* Qg = g_Qh + (size_t)(b * H_ + h) * T_ * HD_;
    const __half* Kg = g_Kh + (size_t)(b * H_ + h) * T_ * HD_;
    const __half* Vg = g_Vh + (size_t)(b * H_ + h) * T_ * HD_;

    const uint32_t a_row = (lane & 7) + ((lane >> 3) & 1) * 8;
    const uint32_t a_col8 = ((lane >> 4) & 1) * 8;
    const uint32_t b_row = (lane & 7) + ((lane >> 4) & 1) * 8;
    const uint32_t b_col8 = ((lane >> 3) & 1) * 8;
    const uint32_t q_off = (uint32_t)(((w * 16 + a_row) * ASQ + a_col8) * 2);
    const uint32_t k_off = (uint32_t)((b_row * ASQ + b_col8) * 2);
    const uint32_t v_off = (uint32_t)((a_row * ASQ + a_col8) * 2);

    auto load_kv = [&](int buf, int k0) {
        #pragma unroll
        for (int i = 0; i < 4; i++) {
            int u = i * 256 + tid;
            int r = u >> 4, c = u & 15;
            cp_async16(kv_b[buf][0] + r * (ASQ * 2) + c * 16,
                       Kg + (size_t)(k0 + r) * HD_ + c * 8);
        }
        #pragma unroll
        for (int i = 0; i < 4; i++) {
            int u = i * 256 + tid;
            int r = u >> 4, c = u & 15;
            cp_async16(kv_b[buf][1] + r * (ASQ * 2) + c * 16,
                       Vg + (size_t)(k0 + r) * HD_ + c * 8);
        }
    };

    #pragma unroll
    for (int i = 0; i < 8; i++) {
        int u = i * 256 + tid;
        int r = u >> 4, c = u & 15;
        cp_async16(qs_b + r * (ASQ * 2) + c * 16,
                   Qg + (size_t)(q0 + r) * HD_ + c * 8);
    }
    load_kv(0, 0);
    CP_ASYNC_COMMIT();

    const int qrow0 = q0 + w * 16 + fr;
    const int qrow1 = qrow0 + 8;

    float m0 = -1e30f, m1 = -1e30f, l0 = 0.f, l1 = 0.f;
    float o[16][4];
    #pragma unroll
    for (int nf = 0; nf < 16; nf++)
        #pragma unroll
        for (int q = 0; q < 4; q++) o[nf][q] = 0.f;

    const int nkt = 2 * qi + 2;
    for (int kt = 0; kt < nkt; kt++) {
        const int k0 = kt * 64;
        const uint32_t ks_u = kv_b[kt & 1][0];
        const uint32_t vs_u = kv_b[kt & 1][1];

        CP_ASYNC_WAIT_ALL();
        __syncthreads();
        if (kt + 1 < nkt)
            load_kv((kt + 1) & 1, k0 + 64);
        CP_ASYNC_COMMIT();

        // ---- S = Q K^T ----
        float s[8][4];
        #pragma unroll
        for (int nf = 0; nf < 8; nf++)
            #pragma unroll
            for (int q = 0; q < 4; q++) s[nf][q] = 0.f;

        #pragma unroll
        for (int ks = 0; ks < 8; ks++) {
            uint32_t a0, a1, a2, a3, bb[4][4];
            ldsm_x4(a0, a1, a2, a3, qs_b + q_off + (uint32_t)(ks * 32));
            #pragma unroll
            for (int nj = 0; nj < 4; nj++)
                ldsm_x4(bb[nj][0], bb[nj][1], bb[nj][2], bb[nj][3],
                        ks_u + k_off + (uint32_t)((nj * 16 * ASQ) * 2 + ks * 32));
            #pragma unroll
            for (int nf = 0; nf < 8; nf++)
                mma_f16(s[nf], a0, a1, a2, a3,
                        bb[nf >> 1][(nf & 1) * 2], bb[nf >> 1][(nf & 1) * 2 + 1]);
        }

        // ---- causal mask ----
        if (kt >= 2 * qi) {
            #pragma unroll
            for (int nf = 0; nf < 8; nf++) {
                int col = k0 + nf * 8 + 2 * tq;
                if (col     > qrow0) s[nf][0] = -1e30f;
                if (col + 1 > qrow0) s[nf][1] = -1e30f;
                if (col     > qrow1) s[nf][2] = -1e30f;
                if (col + 1 > qrow1) s[nf][3] = -1e30f;
            }
        }

        // ---- online softmax ----
        float mx0 = -1e30f, mx1 = -1e30f;
        #pragma unroll
        for (int nf = 0; nf < 8; nf++) {
            mx0 = fmaxf(mx0, fmaxf(s[nf][0], s[nf][1]));
            mx1 = fmaxf(mx1, fmaxf(s[nf][2], s[nf][3]));
        }
        mx0 = fmaxf(mx0, __shfl_xor_sync(0xffffffffu, mx0, 1));
        mx0 = fmaxf(mx0, __shfl_xor_sync(0xffffffffu, mx0, 2));
        mx1 = fmaxf(mx1, __shfl_xor_sync(0xffffffffu, mx1, 1));
        mx1 = fmaxf(mx1, __shfl_xor_sync(0xffffffffu, mx1, 2));

        float mn0 = fmaxf(m0, mx0), mn1 = fmaxf(m1, mx1);
        float al0 = __expf(m0 - mn0), al1 = __expf(m1 - mn1);

        uint32_t pa[4][4];
        float ps0 = 0.f, ps1 = 0.f;
        #pragma unroll
        for (int nf = 0; nf < 8; nf++) {
            float p0 = __expf(s[nf][0] - mn0);
            float p1 = __expf(s[nf][1] - mn0);
            float p2 = __expf(s[nf][2] - mn1);
            float p3 = __expf(s[nf][3] - mn1);
            ps0 += p0 + p1; ps1 += p2 + p3;
            const int ks2 = nf >> 1, lo = (nf & 1) * 2;
            __half2 h01 = __floats2half2_rn(p0, p1);
            __half2 h23 = __floats2half2_rn(p2, p3);
            pa[ks2][lo]     = *reinterpret_cast<uint32_t*>(&h01);
            pa[ks2][lo + 1] = *reinterpret_cast<uint32_t*>(&h23);
        }
        ps0 += __shfl_xor_sync(0xffffffffu, ps0, 1);
        ps0 += __shfl_xor_sync(0xffffffffu, ps0, 2);
        ps1 += __shfl_xor_sync(0xffffffffu, ps1, 1);
        ps1 += __shfl_xor_sync(0xffffffffu, ps1, 2);
        l0 = l0 * al0 + ps0; m0 = mn0;
        l1 = l1 * al1 + ps1; m1 = mn1;

        #pragma unroll
        for (int nf = 0; nf < 16; nf++) {
            o[nf][0] *= al0; o[nf][1] *= al0;
            o[nf][2] *= al1; o[nf][3] *= al1;
        }

        // ---- O += P V : 8 d-tiles cover full HD=128 ----
        #pragma unroll
        for (int ks2 = 0; ks2 < 4; ks2++) {
            #pragma unroll
            for (int nj = 0; nj < 8; nj++) {
                uint32_t r0, r1, r2, r3;
                ldsm_x4_t(r0, r1, r2, r3,
                          vs_u + v_off +
                          (uint32_t)((ks2 * 16 * ASQ + nj * 16) * 2));
                mma_f16(o[nj * 2],     pa[ks2][0], pa[ks2][1], pa[ks2][2], pa[ks2][3], r0, r1);
                mma_f16(o[nj * 2 + 1], pa[ks2][0], pa[ks2][1], pa[ks2][2], pa[ks2][3], r2, r3);
            }
        }
    }

    // ---- epilogue ----
    const float inv0 = 1.f / l0, inv1 = 1.f / l1;
    __half* y0 = g_Yh + (size_t)(b * T_ + qrow0) * C_ + h * HD_;
    __half* y1 = g_Yh + (size_t)(b * T_ + qrow1) * C_ + h * HD_;
    #pragma unroll
    for (int nf = 0; nf < 16; nf++) {
        int c = nf * 8 + 2 * tq;
        *(__half2*)(y0 + c) = __floats2half2_rn(o[nf][0] * inv0, o[nf][1] * inv0);
        *(__half2*)(y1 + c) = __floats2half2_rn(o[nf][2] * inv1, o[nf][3] * inv1);
    }
}

// ---------------------------------------------------------------------------
// Launch. Inputs (metadata order): x, mask, W_qkv, W_proj, b_proj
// ---------------------------------------------------------------------------
extern "C" void kernel_launch(void* const* d_in, const int* in_sizes, int n_in,
                              void* d_out, int out_size) {
    const float* x     = (const float*)d_in[0];
    const float* Wqkv  = (const float*)d_in[2];
    const float* Wproj = (const float*)d_in[3];
    const float* bproj = (const float*)d_in[4];
    float* out = (float*)d_out;

    static bool attr_set = false;
    if (!attr_set) {
        cudaFuncSetAttribute(attn_h,
                             cudaFuncAttributeMaxDynamicSharedMemorySize,
                             ATTN_SMEM_BYTES);
        cudaFuncSetAttribute(gemm_h,
                             cudaFuncAttributeMaxDynamicSharedMemorySize,
                             GEMM_SMEM_BYTES);
        attr_set = true;
    }

    __half* xh;  cudaGetSymbolAddress((void**)&xh,  g_xh);
    __half* wq;  cudaGetSymbolAddress((void**)&wq,  g_Wqkvh);
    __half* wp;  cudaGetSymbolAddress((void**)&wp,  g_Wprojh);
    __half* yh;  cudaGetSymbolAddress((void**)&yh,  g_Yh);

    // Fused pre-pass: all fp32 -> fp16 conversions, one launch
    cvt_all<<<(int)(NTOT / 2048), 256>>>(x, Wqkv, Wproj);

    // QKV projection (fp16 tensor cores), B in native [K,N]; scatter Q/K/V
    gemm_h<<<dim3(NQKV / 128, M_ / 128), 256, GEMM_SMEM_BYTES>>>(
        xh, wq, nullptr, nullptr, C_, NQKV, 1, 0);

    // Attention (fp16 tensor-core flash, causal)
    attn_h<<<dim3(T_ / 128, H_, B_), 256, ATTN_SMEM_BYTES>>>();

    // Output projection (fp16 tensor cores) + fp32 bias
    gemm_h<<<dim3(C_ / 128, M_ / 128), 256, GEMM_SMEM_BYTES>>>(
        yh, wp, bproj, out, C_, C_, 0, C_);
}